// round 6
// baseline (speedup 1.0000x reference)
#include <cuda_runtime.h>

// ---------------------------------------------------------------------------
// KF: batched square-root Kalman filter. B=2048, T=1000, n=d=8.
// Chunked linear-scan (LCH=10), batch-per-thread matvecs, shared-staged
// coalesced Y/traj tiles. Pipeline: riccati -> wprep -> ends -> combine -> scan.
// ---------------------------------------------------------------------------

#define LCH  10
#define TMAX 1024
#define CMAX ((TMAX + LCH - 1) / LCH)
#define BMAX 2048
#define NB   128            // batches per block in ends/scan
#define SROW (LCH * 8 + 4)  // 84 floats = 21 float4 (odd) -> conflict-floor LDS

__device__ __align__(16) float g_AK[TMAX * 128];   // per t: A[64], K[64] (t < tconv)
__device__ __align__(16) float g_W[TMAX * 64];     // suffix weights
__device__ __align__(16) float g_Phi[CMAX * 64];   // chunk transitions
__device__ __align__(16) float g_E[(size_t)CMAX * BMAX * 8];
__device__ __align__(16) float g_X[(size_t)CMAX * BMAX * 8];
__device__ __align__(16) float g_frozen[192];      // A[64], K[64], P[64]
__device__ int   g_tconv;

// ============================ riccati ======================================

__global__ void __launch_bounds__(64) riccati_kernel(
    const float* __restrict__ Fg, const float* __restrict__ Gg,
    const float* __restrict__ Hg, const float* __restrict__ Qg,
    const float* __restrict__ Rg, const float* __restrict__ P0g,
    float* __restrict__ Ps_out, int T)
{
    __shared__ float sF[72], sHF[72], sGQG[72], sC1[72], sC2[72];
    __shared__ float sP[72], sU[72], sV[72], sPn[72], sT2[72], sS[72];
    __shared__ float sK[72], sTmp[72];
    __shared__ float sRed[4];
    __shared__ int   sFlag;

    const int tid = threadIdx.x;
    const int i = tid >> 3, j = tid & 7;
    const int ij = i * 9 + j;

    sF[ij] = Fg[tid]; sTmp[ij] = Gg[tid]; sU[ij] = Qg[tid];
    sC2[ij] = Rg[tid]; sP[ij] = P0g[tid]; sV[ij] = Hg[tid];
    if (tid == 0) sFlag = 0;
    __syncthreads();

    {   // GQ -> sPn ; HF -> sHF
        float a = 0.f, b = 0.f;
        #pragma unroll
        for (int k = 0; k < 8; k++) {
            a += sTmp[i*9+k] * sU[k*9+j];
            b += sV[i*9+k]   * sF[k*9+j];
        }
        sPn[ij] = a; sHF[ij] = b;
    }
    __syncthreads();
    {   // GQG = GQ * G^T
        float a = 0.f;
        #pragma unroll
        for (int k = 0; k < 8; k++) a += sPn[i*9+k] * sTmp[j*9+k];
        sGQG[ij] = a;
    }
    __syncthreads();
    {   // C1 = H * GQG
        float a = 0.f;
        #pragma unroll
        for (int k = 0; k < 8; k++) a += sV[i*9+k] * sGQG[k*9+j];
        sC1[ij] = a;
    }
    __syncthreads();
    {   // C2 = C1 * H^T + R
        float a = sC2[ij];
        #pragma unroll
        for (int k = 0; k < 8; k++) a += sC1[i*9+k] * sV[j*9+k];
        __syncthreads();
        sC2[ij] = a;
    }
    __syncthreads();

    int conv = 0;
    bool frozen = false;
    for (int t = 0; t < T; t++) {
        {   // U = F*P ; V = HF*P
            float a = 0.f, b = 0.f;
            #pragma unroll
            for (int k = 0; k < 8; k++) {
                float p = sP[k*9+j];
                a = fmaf(sF[i*9+k],  p, a);
                b = fmaf(sHF[i*9+k], p, b);
            }
            sU[ij] = a; sV[ij] = b;
        }
        __syncthreads();
        {   // Pn = U*F^T + GQG ; T2 = V*F^T + C1 ; S = V*HF^T + C2
            float pn = sGQG[ij], t2 = sC1[ij], s = sC2[ij];
            #pragma unroll
            for (int k = 0; k < 8; k++) {
                float fk = sF[j*9+k];
                float vk = sV[i*9+k];
                pn = fmaf(sU[i*9+k], fk, pn);
                t2 = fmaf(vk, fk, t2);
                s  = fmaf(vk, sHF[j*9+k], s);
            }
            sPn[ij] = pn; sT2[ij] = t2; sS[ij] = s;
        }
        __syncthreads();
        // Gauss-Jordan on [S | T2]: solves S X = T2 (S SPD, no pivoting).
        if (tid < 16) {
            float a[8];
            #pragma unroll
            for (int r = 0; r < 8; r++)
                a[r] = (tid < 8) ? sS[r*9+tid] : sT2[r*9+(tid-8)];
            #pragma unroll
            for (int p = 0; p < 8; p++) {
                float c[8];
                #pragma unroll
                for (int r = 0; r < 8; r++)
                    c[r] = __shfl_sync(0x0000FFFFu, a[r], p, 16);
                float pr = 1.0f / c[p];
                a[p] *= pr;
                #pragma unroll
                for (int r = 0; r < 8; r++)
                    if (r != p) a[r] = fmaf(-c[r], a[p], a[r]);
            }
            if (tid >= 8) {
                const int row = tid - 8;
                #pragma unroll
                for (int r = 0; r < 8; r++) sK[row*9 + r] = a[r];
            }
        }
        __syncthreads();
        // P+ = Pn - K*T2 ; A = F - K*HF
        float krow[8];
        #pragma unroll
        for (int k = 0; k < 8; k++) krow[k] = sK[i*9+k];
        float pp = sPn[ij], aa = sF[ij];
        #pragma unroll
        for (int k = 0; k < 8; k++) {
            pp = fmaf(-krow[k], sT2[k*9+j], pp);
            aa = fmaf(-krow[k], sHF[k*9+j], aa);
        }
        sTmp[ij] = pp;
        __syncthreads();
        float pnew = 0.5f * (pp + sTmp[j*9+i]);
        float pold = sP[ij];
        sP[ij] = pnew;

        Ps_out[(size_t)t*64 + tid]          = pnew;
        g_AK[(size_t)t*128 + i*8 + j]       = aa;
        g_AK[(size_t)t*128 + 64 + i*8 + j]  = krow[j];

        float dm = fabsf(pnew - pold);
        float pm = fabsf(pnew);
        #pragma unroll
        for (int o = 16; o > 0; o >>= 1) {
            dm = fmaxf(dm, __shfl_xor_sync(0xFFFFFFFFu, dm, o));
            pm = fmaxf(pm, __shfl_xor_sync(0xFFFFFFFFu, pm, o));
        }
        if ((tid & 31) == 0) { sRed[(tid>>5)*2] = dm; sRed[(tid>>5)*2+1] = pm; }
        __syncthreads();
        if (tid == 0) {
            float d = fmaxf(sRed[0], sRed[2]);
            float p = fmaxf(sRed[1], sRed[3]);
            if (t >= 16 && d < 1e-4f * p) conv++; else conv = 0;
            sFlag = (conv >= 3) ? 1 : 0;
        }
        __syncthreads();
        if (sFlag) {
            g_frozen[tid]       = aa;
            g_frozen[64 + tid]  = krow[j];
            g_frozen[128 + tid] = pnew;
            if (tid == 0) g_tconv = t + 1;
            frozen = true;
            break;
        }
    }
    if (!frozen && tid == 0) g_tconv = T;
}

// ======================= shared A/K staging helper =========================

__device__ __forceinline__ void load_sAK(float* sAK, int L0, int Lc, int tconv,
                                         int tid, int nthr)
{
    const float4* gAK4 = (const float4*)g_AK;
    const float4* frz4 = (const float4*)g_frozen;
    for (int e = tid; e < Lc * 32; e += nthr) {
        const int t = L0 + (e >> 5);
        const int q = e & 31;
        ((float4*)sAK)[e] = (t < tconv) ? gAK4[(size_t)t * 32 + q] : frz4[q];
    }
}

// ============================ wprep ========================================
// Per chunk: suffix weights W, transition Phi, frozen Ps tail.

__global__ void __launch_bounds__(64) wprep_kernel(float* __restrict__ Ps_out, int T)
{
    const int c  = blockIdx.x;
    const int L0 = c * LCH;
    const int Lc = min(LCH, T - L0);
    const int tconv = g_tconv;

    __shared__ __align__(16) float sAK[LCH * 128];
    __shared__ float sM[2][72];

    const int tid = threadIdx.x;
    const int i = tid >> 3, j = tid & 7;
    load_sAK(sAK, L0, Lc, tconv, tid, 64);
    sM[0][i*9+j] = (i == j) ? 1.f : 0.f;

    // frozen Ps tail
    for (int t = max(L0, tconv); t < L0 + Lc; t++)
        Ps_out[(size_t)t*64 + tid] = g_frozen[128 + tid];
    __syncthreads();

    int pb = 0;
    for (int jj = Lc - 1; jj >= 0; jj--) {
        const float* a = sAK + jj * 128;
        float w = 0.f, m = 0.f;
        #pragma unroll
        for (int k = 0; k < 8; k++) {
            float mk = sM[pb][i*9+k];
            w = fmaf(mk, a[64 + k*8 + j], w);
            m = fmaf(mk, a[k*8 + j],      m);
        }
        g_W[(size_t)(L0 + jj)*64 + tid] = w;
        sM[pb ^ 1][i*9+j] = m;
        pb ^= 1;
        __syncthreads();
    }
    g_Phi[c*64 + tid] = sM[pb][i*9+j];
}

// ====================== Y tile staging helpers =============================

__device__ __forceinline__ void stage_Y_in(float* sY, const float* __restrict__ Y,
                                           int b0, int L0, int Lc, int B, int T,
                                           int tid)
{
    const float4* Y4 = (const float4*)Y;
    for (int idx = tid; idx < NB * 2 * LCH; idx += NB) {
        const int row = idx / (2 * LCH);
        const int col = idx - row * (2 * LCH);
        const int b = b0 + row;
        if (b < B && col < 2 * Lc)
            ((float4*)(sY + row * SROW))[col] = Y4[((size_t)b * T + L0) * 2 + col];
    }
}

__device__ __forceinline__ void stage_out(const float* sY, float* __restrict__ traj,
                                          int b0, int L0, int Lc, int B, int T,
                                          int tid)
{
    float4* T4 = (float4*)traj;
    for (int idx = tid; idx < NB * 2 * LCH; idx += NB) {
        const int row = idx / (2 * LCH);
        const int col = idx - row * (2 * LCH);
        const int b = b0 + row;
        if (b < B && col < 2 * Lc)
            T4[((size_t)b * T + L0) * 2 + col] = ((const float4*)(sY + row * SROW))[col];
    }
}

// ============================ ends =========================================
// e_{c,b} = sum_j W_{c,j} y_{c,j}; Y staged through shared (coalesced).

__global__ void __launch_bounds__(NB) ends_kernel(
    const float* __restrict__ Y, int B, int T)
{
    const int c  = blockIdx.x;
    const int L0 = c * LCH;
    const int Lc = min(LCH, T - L0);

    __shared__ __align__(16) float sW[LCH * 64];
    __shared__ __align__(16) float sY[NB * SROW];

    const int tid = threadIdx.x;
    for (int e = tid; e < Lc * 16; e += NB)
        ((float4*)sW)[e] = ((const float4*)(g_W + (size_t)L0 * 64))[e];
    stage_Y_in(sY, Y, blockIdx.y * NB, L0, Lc, B, T, tid);
    __syncthreads();

    const int b = blockIdx.y * NB + tid;
    const float* myY = sY + tid * SROW;

    float acc[8];
    #pragma unroll
    for (int i = 0; i < 8; i++) acc[i] = 0.f;

    #pragma unroll
    for (int jj = 0; jj < LCH; jj++) {
        if (jj < Lc) {
            const float4 y0 = ((const float4*)myY)[2*jj];
            const float4 y1 = ((const float4*)myY)[2*jj + 1];
            const float* w = sW + jj * 64;
            #pragma unroll
            for (int i = 0; i < 8; i++) {
                float a = acc[i];
                a = fmaf(w[i*8+0], y0.x, a); a = fmaf(w[i*8+1], y0.y, a);
                a = fmaf(w[i*8+2], y0.z, a); a = fmaf(w[i*8+3], y0.w, a);
                a = fmaf(w[i*8+4], y1.x, a); a = fmaf(w[i*8+5], y1.y, a);
                a = fmaf(w[i*8+6], y1.z, a); a = fmaf(w[i*8+7], y1.w, a);
                acc[i] = a;
            }
        }
    }
    if (b < B) {
        float4* eo = (float4*)(g_E + ((size_t)c * B + b) * 8);
        eo[0] = make_float4(acc[0], acc[1], acc[2], acc[3]);
        eo[1] = make_float4(acc[4], acc[5], acc[6], acc[7]);
    }
}

// ============================ combine ======================================

__global__ void __launch_bounds__(256) combine_kernel(
    const float* __restrict__ x0, int B, int C)
{
    __shared__ float sPhi[CMAX * 64];
    const int tid = threadIdx.x;
    for (int e = tid; e < C * 64; e += 256) sPhi[e] = g_Phi[e];
    __syncthreads();

    const int b = blockIdx.x * 256 + tid;
    const bool ok = (b < B);
    const int bs = ok ? b : 0;

    float x[8];
    {
        const float4* xp = (const float4*)(x0 + bs * 8);
        float4 a = xp[0], b4 = xp[1];
        x[0]=a.x; x[1]=a.y; x[2]=a.z; x[3]=a.w;
        x[4]=b4.x; x[5]=b4.y; x[6]=b4.z; x[7]=b4.w;
    }

    float4 r0[4], r1[4];
    #pragma unroll
    for (int p = 0; p < 3; p++) {
        const int cc = (p < C) ? p : C - 1;
        const float4* ep = (const float4*)(g_E + ((size_t)cc * B + bs) * 8);
        r0[p] = ep[0]; r1[p] = ep[1];
    }

    for (int c = 0; c < C; c++) {
        if (ok) {
            float4* xo = (float4*)(g_X + ((size_t)c * B + b) * 8);
            xo[0] = make_float4(x[0], x[1], x[2], x[3]);
            xo[1] = make_float4(x[4], x[5], x[6], x[7]);
        }
        const int s = c & 3;
        const float4 e0 = r0[s], e1 = r1[s];
        {   // prefetch c+3
            const int cn = c + 3;
            const int cc = (cn < C) ? cn : C - 1;
            const float4* ep = (const float4*)(g_E + ((size_t)cc * B + bs) * 8);
            r0[cn & 3] = ep[0]; r1[cn & 3] = ep[1];
        }
        const float* pr = sPhi + c * 64;
        float xn[8];
        #pragma unroll
        for (int i = 0; i < 8; i++) {
            float a = 0.f;
            #pragma unroll
            for (int k = 0; k < 8; k++) a = fmaf(pr[i*8+k], x[k], a);
            xn[i] = a;
        }
        xn[0]+=e0.x; xn[1]+=e0.y; xn[2]+=e0.z; xn[3]+=e0.w;
        xn[4]+=e1.x; xn[5]+=e1.y; xn[6]+=e1.z; xn[7]+=e1.w;
        #pragma unroll
        for (int i = 0; i < 8; i++) x[i] = xn[i];
    }
}

// ============================ scan =========================================
// x_t = A_t x + K_t y; Y staged in, outputs overwrite the tile, staged out.

__global__ void __launch_bounds__(NB) scan_kernel(
    const float* __restrict__ Y, float* __restrict__ traj, int B, int T)
{
    const int c  = blockIdx.x;
    const int L0 = c * LCH;
    const int Lc = min(LCH, T - L0);
    const int tconv = g_tconv;

    __shared__ __align__(16) float sAK[LCH * 128];
    __shared__ __align__(16) float sY[NB * SROW];

    const int tid = threadIdx.x;
    load_sAK(sAK, L0, Lc, tconv, tid, NB);
    stage_Y_in(sY, Y, blockIdx.y * NB, L0, Lc, B, T, tid);
    __syncthreads();

    const int b = blockIdx.y * NB + tid;
    const int bs = (b < B) ? b : 0;
    float* myY = sY + tid * SROW;

    float x[8];
    {
        const float4* xp = (const float4*)(g_X + ((size_t)c * B + bs) * 8);
        float4 a = xp[0], b4 = xp[1];
        x[0]=a.x; x[1]=a.y; x[2]=a.z; x[3]=a.w;
        x[4]=b4.x; x[5]=b4.y; x[6]=b4.z; x[7]=b4.w;
    }

    #pragma unroll
    for (int jj = 0; jj < LCH; jj++) {
        if (jj < Lc) {
            const float4 y0 = ((const float4*)myY)[2*jj];
            const float4 y1 = ((const float4*)myY)[2*jj + 1];
            const float* a = sAK + jj * 128;      // A [0..63], K [64..127]
            float xn[8];
            #pragma unroll
            for (int i = 0; i < 8; i++) {
                const float* ar = a + i * 8;
                const float* kr = a + 64 + i * 8;
                float s0 = ar[0] * x[0];
                float s1 = kr[0] * y0.x;
                s0 = fmaf(ar[1], x[1], s0);  s1 = fmaf(kr[1], y0.y, s1);
                s0 = fmaf(ar[2], x[2], s0);  s1 = fmaf(kr[2], y0.z, s1);
                s0 = fmaf(ar[3], x[3], s0);  s1 = fmaf(kr[3], y0.w, s1);
                s0 = fmaf(ar[4], x[4], s0);  s1 = fmaf(kr[4], y1.x, s1);
                s0 = fmaf(ar[5], x[5], s0);  s1 = fmaf(kr[5], y1.y, s1);
                s0 = fmaf(ar[6], x[6], s0);  s1 = fmaf(kr[6], y1.z, s1);
                s0 = fmaf(ar[7], x[7], s0);  s1 = fmaf(kr[7], y1.w, s1);
                xn[i] = s0 + s1;
            }
            #pragma unroll
            for (int i = 0; i < 8; i++) x[i] = xn[i];
            ((float4*)myY)[2*jj]     = make_float4(x[0], x[1], x[2], x[3]);
            ((float4*)myY)[2*jj + 1] = make_float4(x[4], x[5], x[6], x[7]);
        }
    }
    __syncthreads();
    stage_out(sY, traj, blockIdx.y * NB, L0, Lc, B, T, tid);
}

// ============================ launch =======================================

extern "C" void kernel_launch(void* const* d_in, const int* in_sizes, int n_in,
                              void* d_out, int out_size)
{
    const float* Y  = (const float*)d_in[0];
    const float* F  = (const float*)d_in[1];
    const float* G  = (const float*)d_in[2];
    const float* H  = (const float*)d_in[3];
    const float* Q  = (const float*)d_in[4];
    const float* R  = (const float*)d_in[5];
    const float* x0 = (const float*)d_in[6];
    const float* P0 = (const float*)d_in[7];

    const int B = in_sizes[6] / 8;
    const int T = in_sizes[0] / (B * 8);
    const int C = (T + LCH - 1) / LCH;

    float* traj = (float*)d_out;                 // (B, T, 8)
    float* Ps   = traj + (size_t)B * T * 8;      // (T, 8, 8)

    riccati_kernel<<<1, 64>>>(F, G, H, Q, R, P0, Ps, T);
    wprep_kernel<<<C, 64>>>(Ps, T);
    {
        dim3 grid(C, (B + NB - 1) / NB);
        ends_kernel<<<grid, NB>>>(Y, B, T);
    }
    combine_kernel<<<(B + 255) / 256, 256>>>(x0, B, C);
    {
        dim3 grid(C, (B + NB - 1) / NB);
        scan_kernel<<<grid, NB>>>(Y, traj, B, T);
    }
}

// round 7
// speedup vs baseline: 1.2234x; 1.2234x over previous
#include <cuda_runtime.h>

// ---------------------------------------------------------------------------
// KF: batched square-root Kalman filter. B=2048, T=1000, n=d=8.
// Two-level chunked linear-scan: LCH=10 time-steps/chunk, SL=10 chunks/super.
// Pipeline: riccati -> wprep -> [ends, wprep2] -> combineA -> combineB
//           -> combineC -> scan.
// ---------------------------------------------------------------------------

#define LCH  10
#define SL   10
#define TMAX 1024
#define CMAX ((TMAX + LCH - 1) / LCH)
#define SCMAX ((CMAX + SL - 1) / SL)
#define BMAX 2048
#define NB   128            // batches per block in ends/scan/combineA/C
#define SROW (LCH * 8 + 4)  // 84 floats = 21 float4 (odd) -> conflict-floor LDS

__device__ __align__(16) float g_AK[TMAX * 128];   // per t: A[64], K[64] (t < tconv)
__device__ __align__(16) float g_W[TMAX * 64];     // per-step suffix weights
__device__ __align__(16) float g_Phi[CMAX * 64];   // chunk transitions
__device__ __align__(16) float g_W2[CMAX * 64];    // chunk-level suffix weights
__device__ __align__(16) float g_Psi[SCMAX * 64];  // super-chunk transitions
__device__ __align__(16) float g_E [(size_t)CMAX  * BMAX * 8];
__device__ __align__(16) float g_E2[(size_t)SCMAX * BMAX * 8];
__device__ __align__(16) float g_X [(size_t)CMAX  * BMAX * 8];
__device__ __align__(16) float g_X2[(size_t)SCMAX * BMAX * 8];
__device__ __align__(16) float g_frozen[192];      // A[64], K[64], P[64]
__device__ int   g_tconv;

// ============================ riccati ======================================

__global__ void __launch_bounds__(64) riccati_kernel(
    const float* __restrict__ Fg, const float* __restrict__ Gg,
    const float* __restrict__ Hg, const float* __restrict__ Qg,
    const float* __restrict__ Rg, const float* __restrict__ P0g,
    float* __restrict__ Ps_out, int T)
{
    __shared__ float sF[72], sHF[72], sGQG[72], sC1[72], sC2[72];
    __shared__ float sP[72], sU[72], sV[72], sPn[72], sT2[72], sS[72];
    __shared__ float sK[72], sTmp[72];
    __shared__ float sRed[4];
    __shared__ int   sFlag;

    const int tid = threadIdx.x;
    const int i = tid >> 3, j = tid & 7;
    const int ij = i * 9 + j;

    sF[ij] = Fg[tid]; sTmp[ij] = Gg[tid]; sU[ij] = Qg[tid];
    sC2[ij] = Rg[tid]; sP[ij] = P0g[tid]; sV[ij] = Hg[tid];
    if (tid == 0) sFlag = 0;
    __syncthreads();

    {   // GQ -> sPn ; HF -> sHF
        float a = 0.f, b = 0.f;
        #pragma unroll
        for (int k = 0; k < 8; k++) {
            a += sTmp[i*9+k] * sU[k*9+j];
            b += sV[i*9+k]   * sF[k*9+j];
        }
        sPn[ij] = a; sHF[ij] = b;
    }
    __syncthreads();
    {   // GQG = GQ * G^T
        float a = 0.f;
        #pragma unroll
        for (int k = 0; k < 8; k++) a += sPn[i*9+k] * sTmp[j*9+k];
        sGQG[ij] = a;
    }
    __syncthreads();
    {   // C1 = H * GQG
        float a = 0.f;
        #pragma unroll
        for (int k = 0; k < 8; k++) a += sV[i*9+k] * sGQG[k*9+j];
        sC1[ij] = a;
    }
    __syncthreads();
    {   // C2 = C1 * H^T + R
        float a = sC2[ij];
        #pragma unroll
        for (int k = 0; k < 8; k++) a += sC1[i*9+k] * sV[j*9+k];
        __syncthreads();
        sC2[ij] = a;
    }
    __syncthreads();

    int conv = 0;
    bool frozen = false;
    for (int t = 0; t < T; t++) {
        {   // U = F*P ; V = HF*P
            float a = 0.f, b = 0.f;
            #pragma unroll
            for (int k = 0; k < 8; k++) {
                float p = sP[k*9+j];
                a = fmaf(sF[i*9+k],  p, a);
                b = fmaf(sHF[i*9+k], p, b);
            }
            sU[ij] = a; sV[ij] = b;
        }
        __syncthreads();
        {   // Pn = U*F^T + GQG ; T2 = V*F^T + C1 ; S = V*HF^T + C2
            float pn = sGQG[ij], t2 = sC1[ij], s = sC2[ij];
            #pragma unroll
            for (int k = 0; k < 8; k++) {
                float fk = sF[j*9+k];
                float vk = sV[i*9+k];
                pn = fmaf(sU[i*9+k], fk, pn);
                t2 = fmaf(vk, fk, t2);
                s  = fmaf(vk, sHF[j*9+k], s);
            }
            sPn[ij] = pn; sT2[ij] = t2; sS[ij] = s;
        }
        __syncthreads();
        // Gauss-Jordan on [S | T2]: solves S X = T2 (S SPD, no pivoting).
        if (tid < 16) {
            float a[8];
            #pragma unroll
            for (int r = 0; r < 8; r++)
                a[r] = (tid < 8) ? sS[r*9+tid] : sT2[r*9+(tid-8)];
            #pragma unroll
            for (int p = 0; p < 8; p++) {
                float c[8];
                #pragma unroll
                for (int r = 0; r < 8; r++)
                    c[r] = __shfl_sync(0x0000FFFFu, a[r], p, 16);
                float pr = 1.0f / c[p];
                a[p] *= pr;
                #pragma unroll
                for (int r = 0; r < 8; r++)
                    if (r != p) a[r] = fmaf(-c[r], a[p], a[r]);
            }
            if (tid >= 8) {
                const int row = tid - 8;
                #pragma unroll
                for (int r = 0; r < 8; r++) sK[row*9 + r] = a[r];
            }
        }
        __syncthreads();
        // P+ = Pn - K*T2 ; A = F - K*HF
        float krow[8];
        #pragma unroll
        for (int k = 0; k < 8; k++) krow[k] = sK[i*9+k];
        float pp = sPn[ij], aa = sF[ij];
        #pragma unroll
        for (int k = 0; k < 8; k++) {
            pp = fmaf(-krow[k], sT2[k*9+j], pp);
            aa = fmaf(-krow[k], sHF[k*9+j], aa);
        }
        sTmp[ij] = pp;
        __syncthreads();
        float pnew = 0.5f * (pp + sTmp[j*9+i]);
        float pold = sP[ij];
        sP[ij] = pnew;

        Ps_out[(size_t)t*64 + tid]          = pnew;
        g_AK[(size_t)t*128 + i*8 + j]       = aa;
        g_AK[(size_t)t*128 + 64 + i*8 + j]  = krow[j];

        float dm = fabsf(pnew - pold);
        float pm = fabsf(pnew);
        #pragma unroll
        for (int o = 16; o > 0; o >>= 1) {
            dm = fmaxf(dm, __shfl_xor_sync(0xFFFFFFFFu, dm, o));
            pm = fmaxf(pm, __shfl_xor_sync(0xFFFFFFFFu, pm, o));
        }
        if ((tid & 31) == 0) { sRed[(tid>>5)*2] = dm; sRed[(tid>>5)*2+1] = pm; }
        __syncthreads();
        if (tid == 0) {
            float d = fmaxf(sRed[0], sRed[2]);
            float p = fmaxf(sRed[1], sRed[3]);
            if (t >= 12 && d < 2e-4f * p) conv++; else conv = 0;
            sFlag = (conv >= 2) ? 1 : 0;
        }
        __syncthreads();
        if (sFlag) {
            g_frozen[tid]       = aa;
            g_frozen[64 + tid]  = krow[j];
            g_frozen[128 + tid] = pnew;
            if (tid == 0) g_tconv = t + 1;
            frozen = true;
            break;
        }
    }
    if (!frozen && tid == 0) g_tconv = T;
}

// ======================= shared A/K staging helper =========================

__device__ __forceinline__ void load_sAK(float* sAK, int L0, int Lc, int tconv,
                                         int tid, int nthr)
{
    const float4* gAK4 = (const float4*)g_AK;
    const float4* frz4 = (const float4*)g_frozen;
    for (int e = tid; e < Lc * 32; e += nthr) {
        const int t = L0 + (e >> 5);
        const int q = e & 31;
        ((float4*)sAK)[e] = (t < tconv) ? gAK4[(size_t)t * 32 + q] : frz4[q];
    }
}

// ============================ wprep ========================================
// Per chunk: per-step suffix weights W, chunk transition Phi, frozen Ps tail.

__global__ void __launch_bounds__(64) wprep_kernel(float* __restrict__ Ps_out, int T)
{
    const int c  = blockIdx.x;
    const int L0 = c * LCH;
    const int Lc = min(LCH, T - L0);
    const int tconv = g_tconv;

    __shared__ __align__(16) float sAK[LCH * 128];
    __shared__ float sM[2][72];

    const int tid = threadIdx.x;
    const int i = tid >> 3, j = tid & 7;
    load_sAK(sAK, L0, Lc, tconv, tid, 64);
    sM[0][i*9+j] = (i == j) ? 1.f : 0.f;

    for (int t = max(L0, tconv); t < L0 + Lc; t++)
        Ps_out[(size_t)t*64 + tid] = g_frozen[128 + tid];
    __syncthreads();

    int pb = 0;
    for (int jj = Lc - 1; jj >= 0; jj--) {
        const float* a = sAK + jj * 128;
        float w = 0.f, m = 0.f;
        #pragma unroll
        for (int k = 0; k < 8; k++) {
            float mk = sM[pb][i*9+k];
            w = fmaf(mk, a[64 + k*8 + j], w);
            m = fmaf(mk, a[k*8 + j],      m);
        }
        g_W[(size_t)(L0 + jj)*64 + tid] = w;
        sM[pb ^ 1][i*9+j] = m;
        pb ^= 1;
        __syncthreads();
    }
    g_Phi[c*64 + tid] = sM[pb][i*9+j];
}

// ============================ wprep2 =======================================
// Per super-chunk: chunk-level suffix weights W2 and super transition Psi.

__global__ void __launch_bounds__(64) wprep2_kernel(int C)
{
    const int s  = blockIdx.x;
    const int c0 = s * SL;
    const int nc = min(SL, C - c0);
    __shared__ float sM[2][72];
    __shared__ float sPhi[SL * 64];

    const int tid = threadIdx.x;
    const int i = tid >> 3, j = tid & 7;
    for (int e = tid; e < nc * 64; e += 64) sPhi[e] = g_Phi[c0 * 64 + e];
    sM[0][i*9+j] = (i == j) ? 1.f : 0.f;
    __syncthreads();

    int pb = 0;
    for (int jj = nc - 1; jj >= 0; jj--) {
        g_W2[(c0 + jj)*64 + tid] = sM[pb][i*9+j];
        const float* ph = sPhi + jj * 64;
        float m = 0.f;
        #pragma unroll
        for (int k = 0; k < 8; k++)
            m = fmaf(sM[pb][i*9+k], ph[k*8 + j], m);
        sM[pb ^ 1][i*9+j] = m;
        pb ^= 1;
        __syncthreads();
    }
    g_Psi[s*64 + tid] = sM[pb][i*9+j];
}

// ====================== Y tile staging helpers =============================

__device__ __forceinline__ void stage_Y_in(float* sY, const float* __restrict__ Y,
                                           int b0, int L0, int Lc, int B, int T,
                                           int tid)
{
    const float4* Y4 = (const float4*)Y;
    for (int idx = tid; idx < NB * 2 * LCH; idx += NB) {
        const int row = idx / (2 * LCH);
        const int col = idx - row * (2 * LCH);
        const int b = b0 + row;
        if (b < B && col < 2 * Lc)
            ((float4*)(sY + row * SROW))[col] = Y4[((size_t)b * T + L0) * 2 + col];
    }
}

__device__ __forceinline__ void stage_out(const float* sY, float* __restrict__ traj,
                                          int b0, int L0, int Lc, int B, int T,
                                          int tid)
{
    float4* T4 = (float4*)traj;
    for (int idx = tid; idx < NB * 2 * LCH; idx += NB) {
        const int row = idx / (2 * LCH);
        const int col = idx - row * (2 * LCH);
        const int b = b0 + row;
        if (b < B && col < 2 * Lc)
            T4[((size_t)b * T + L0) * 2 + col] = ((const float4*)(sY + row * SROW))[col];
    }
}

// ============================ ends =========================================

__global__ void __launch_bounds__(NB) ends_kernel(
    const float* __restrict__ Y, int B, int T)
{
    const int c  = blockIdx.x;
    const int L0 = c * LCH;
    const int Lc = min(LCH, T - L0);

    __shared__ __align__(16) float sW[LCH * 64];
    __shared__ __align__(16) float sY[NB * SROW];

    const int tid = threadIdx.x;
    for (int e = tid; e < Lc * 16; e += NB)
        ((float4*)sW)[e] = ((const float4*)(g_W + (size_t)L0 * 64))[e];
    stage_Y_in(sY, Y, blockIdx.y * NB, L0, Lc, B, T, tid);
    __syncthreads();

    const int b = blockIdx.y * NB + tid;
    const float* myY = sY + tid * SROW;

    float acc[8];
    #pragma unroll
    for (int i = 0; i < 8; i++) acc[i] = 0.f;

    #pragma unroll
    for (int jj = 0; jj < LCH; jj++) {
        if (jj < Lc) {
            const float4 y0 = ((const float4*)myY)[2*jj];
            const float4 y1 = ((const float4*)myY)[2*jj + 1];
            const float* w = sW + jj * 64;
            #pragma unroll
            for (int i = 0; i < 8; i++) {
                float a = acc[i];
                a = fmaf(w[i*8+0], y0.x, a); a = fmaf(w[i*8+1], y0.y, a);
                a = fmaf(w[i*8+2], y0.z, a); a = fmaf(w[i*8+3], y0.w, a);
                a = fmaf(w[i*8+4], y1.x, a); a = fmaf(w[i*8+5], y1.y, a);
                a = fmaf(w[i*8+6], y1.z, a); a = fmaf(w[i*8+7], y1.w, a);
                acc[i] = a;
            }
        }
    }
    if (b < B) {
        float4* eo = (float4*)(g_E + ((size_t)c * B + b) * 8);
        eo[0] = make_float4(acc[0], acc[1], acc[2], acc[3]);
        eo[1] = make_float4(acc[4], acc[5], acc[6], acc[7]);
    }
}

// ============================ combineA =====================================
// E2_{s,b} = sum_j W2_{s,j} e_{s*SL+j, b}  (parallel accumulation).

__global__ void __launch_bounds__(NB) combineA_kernel(int B, int C)
{
    const int s  = blockIdx.x;
    const int c0 = s * SL;
    const int nc = min(SL, C - c0);

    __shared__ __align__(16) float sW2[SL * 64];
    const int tid = threadIdx.x;
    for (int e = tid; e < nc * 16; e += NB)
        ((float4*)sW2)[e] = ((const float4*)(g_W2 + c0 * 64))[e];
    __syncthreads();

    const int b = blockIdx.y * NB + tid;
    const bool ok = (b < B);
    const int bs = ok ? b : 0;

    float acc[8];
    #pragma unroll
    for (int i = 0; i < 8; i++) acc[i] = 0.f;

    for (int jj = 0; jj < nc; jj++) {
        const float4* ep = (const float4*)(g_E + ((size_t)(c0 + jj) * B + bs) * 8);
        const float4 e0 = ep[0], e1 = ep[1];
        const float* w = sW2 + jj * 64;
        #pragma unroll
        for (int i = 0; i < 8; i++) {
            float a = acc[i];
            a = fmaf(w[i*8+0], e0.x, a); a = fmaf(w[i*8+1], e0.y, a);
            a = fmaf(w[i*8+2], e0.z, a); a = fmaf(w[i*8+3], e0.w, a);
            a = fmaf(w[i*8+4], e1.x, a); a = fmaf(w[i*8+5], e1.y, a);
            a = fmaf(w[i*8+6], e1.z, a); a = fmaf(w[i*8+7], e1.w, a);
            acc[i] = a;
        }
    }
    if (ok) {
        float4* eo = (float4*)(g_E2 + ((size_t)s * B + b) * 8);
        eo[0] = make_float4(acc[0], acc[1], acc[2], acc[3]);
        eo[1] = make_float4(acc[4], acc[5], acc[6], acc[7]);
    }
}

// ============================ combineB =====================================
// Super-chunk entry states: serial over SC (~10) supers per batch.

__global__ void __launch_bounds__(256) combineB_kernel(
    const float* __restrict__ x0, int B, int SC)
{
    __shared__ float sPsi[SCMAX * 64];
    const int tid = threadIdx.x;
    for (int e = tid; e < SC * 64; e += 256) sPsi[e] = g_Psi[e];
    __syncthreads();

    const int b = blockIdx.x * 256 + tid;
    const bool ok = (b < B);
    const int bs = ok ? b : 0;

    float x[8];
    {
        const float4* xp = (const float4*)(x0 + bs * 8);
        float4 a = xp[0], b4 = xp[1];
        x[0]=a.x; x[1]=a.y; x[2]=a.z; x[3]=a.w;
        x[4]=b4.x; x[5]=b4.y; x[6]=b4.z; x[7]=b4.w;
    }

    for (int s = 0; s < SC; s++) {
        if (ok) {
            float4* xo = (float4*)(g_X2 + ((size_t)s * B + b) * 8);
            xo[0] = make_float4(x[0], x[1], x[2], x[3]);
            xo[1] = make_float4(x[4], x[5], x[6], x[7]);
        }
        const float4* ep = (const float4*)(g_E2 + ((size_t)s * B + bs) * 8);
        const float4 e0 = ep[0], e1 = ep[1];
        const float* pr = sPsi + s * 64;
        float xn[8];
        #pragma unroll
        for (int i = 0; i < 8; i++) {
            float a = 0.f;
            #pragma unroll
            for (int k = 0; k < 8; k++) a = fmaf(pr[i*8+k], x[k], a);
            xn[i] = a;
        }
        xn[0]+=e0.x; xn[1]+=e0.y; xn[2]+=e0.z; xn[3]+=e0.w;
        xn[4]+=e1.x; xn[5]+=e1.y; xn[6]+=e1.z; xn[7]+=e1.w;
        #pragma unroll
        for (int i = 0; i < 8; i++) x[i] = xn[i];
    }
}

// ============================ combineC =====================================
// Chunk entry states within each super-chunk (parallel over supers).

__global__ void __launch_bounds__(NB) combineC_kernel(int B, int C)
{
    const int s  = blockIdx.x;
    const int c0 = s * SL;
    const int nc = min(SL, C - c0);

    __shared__ __align__(16) float sPhi[SL * 64];
    const int tid = threadIdx.x;
    for (int e = tid; e < nc * 16; e += NB)
        ((float4*)sPhi)[e] = ((const float4*)(g_Phi + c0 * 64))[e];
    __syncthreads();

    const int b = blockIdx.y * NB + tid;
    const bool ok = (b < B);
    const int bs = ok ? b : 0;

    float x[8];
    {
        const float4* xp = (const float4*)(g_X2 + ((size_t)s * B + bs) * 8);
        float4 a = xp[0], b4 = xp[1];
        x[0]=a.x; x[1]=a.y; x[2]=a.z; x[3]=a.w;
        x[4]=b4.x; x[5]=b4.y; x[6]=b4.z; x[7]=b4.w;
    }

    for (int jj = 0; jj < nc; jj++) {
        const int c = c0 + jj;
        if (ok) {
            float4* xo = (float4*)(g_X + ((size_t)c * B + b) * 8);
            xo[0] = make_float4(x[0], x[1], x[2], x[3]);
            xo[1] = make_float4(x[4], x[5], x[6], x[7]);
        }
        if (jj < nc - 1) {
            const float4* ep = (const float4*)(g_E + ((size_t)c * B + bs) * 8);
            const float4 e0 = ep[0], e1 = ep[1];
            const float* pr = sPhi + jj * 64;
            float xn[8];
            #pragma unroll
            for (int i = 0; i < 8; i++) {
                float a = 0.f;
                #pragma unroll
                for (int k = 0; k < 8; k++) a = fmaf(pr[i*8+k], x[k], a);
                xn[i] = a;
            }
            xn[0]+=e0.x; xn[1]+=e0.y; xn[2]+=e0.z; xn[3]+=e0.w;
            xn[4]+=e1.x; xn[5]+=e1.y; xn[6]+=e1.z; xn[7]+=e1.w;
            #pragma unroll
            for (int i = 0; i < 8; i++) x[i] = xn[i];
        }
    }
}

// ============================ scan =========================================

__global__ void __launch_bounds__(NB) scan_kernel(
    const float* __restrict__ Y, float* __restrict__ traj, int B, int T)
{
    const int c  = blockIdx.x;
    const int L0 = c * LCH;
    const int Lc = min(LCH, T - L0);
    const int tconv = g_tconv;

    __shared__ __align__(16) float sAK[LCH * 128];
    __shared__ __align__(16) float sY[NB * SROW];

    const int tid = threadIdx.x;
    load_sAK(sAK, L0, Lc, tconv, tid, NB);
    stage_Y_in(sY, Y, blockIdx.y * NB, L0, Lc, B, T, tid);
    __syncthreads();

    const int b = blockIdx.y * NB + tid;
    const int bs = (b < B) ? b : 0;
    float* myY = sY + tid * SROW;

    float x[8];
    {
        const float4* xp = (const float4*)(g_X + ((size_t)c * B + bs) * 8);
        float4 a = xp[0], b4 = xp[1];
        x[0]=a.x; x[1]=a.y; x[2]=a.z; x[3]=a.w;
        x[4]=b4.x; x[5]=b4.y; x[6]=b4.z; x[7]=b4.w;
    }

    #pragma unroll
    for (int jj = 0; jj < LCH; jj++) {
        if (jj < Lc) {
            const float4 y0 = ((const float4*)myY)[2*jj];
            const float4 y1 = ((const float4*)myY)[2*jj + 1];
            const float* a = sAK + jj * 128;      // A [0..63], K [64..127]
            float xn[8];
            #pragma unroll
            for (int i = 0; i < 8; i++) {
                const float* ar = a + i * 8;
                const float* kr = a + 64 + i * 8;
                float s0 = ar[0] * x[0];
                float s1 = kr[0] * y0.x;
                s0 = fmaf(ar[1], x[1], s0);  s1 = fmaf(kr[1], y0.y, s1);
                s0 = fmaf(ar[2], x[2], s0);  s1 = fmaf(kr[2], y0.z, s1);
                s0 = fmaf(ar[3], x[3], s0);  s1 = fmaf(kr[3], y0.w, s1);
                s0 = fmaf(ar[4], x[4], s0);  s1 = fmaf(kr[4], y1.x, s1);
                s0 = fmaf(ar[5], x[5], s0);  s1 = fmaf(kr[5], y1.y, s1);
                s0 = fmaf(ar[6], x[6], s0);  s1 = fmaf(kr[6], y1.z, s1);
                s0 = fmaf(ar[7], x[7], s0);  s1 = fmaf(kr[7], y1.w, s1);
                xn[i] = s0 + s1;
            }
            #pragma unroll
            for (int i = 0; i < 8; i++) x[i] = xn[i];
            ((float4*)myY)[2*jj]     = make_float4(x[0], x[1], x[2], x[3]);
            ((float4*)myY)[2*jj + 1] = make_float4(x[4], x[5], x[6], x[7]);
        }
    }
    __syncthreads();
    stage_out(sY, traj, blockIdx.y * NB, L0, Lc, B, T, tid);
}

// ============================ launch =======================================

extern "C" void kernel_launch(void* const* d_in, const int* in_sizes, int n_in,
                              void* d_out, int out_size)
{
    const float* Y  = (const float*)d_in[0];
    const float* F  = (const float*)d_in[1];
    const float* G  = (const float*)d_in[2];
    const float* H  = (const float*)d_in[3];
    const float* Q  = (const float*)d_in[4];
    const float* R  = (const float*)d_in[5];
    const float* x0 = (const float*)d_in[6];
    const float* P0 = (const float*)d_in[7];

    const int B  = in_sizes[6] / 8;
    const int T  = in_sizes[0] / (B * 8);
    const int C  = (T + LCH - 1) / LCH;
    const int SC = (C + SL - 1) / SL;
    const int GB = (B + NB - 1) / NB;

    float* traj = (float*)d_out;                 // (B, T, 8)
    float* Ps   = traj + (size_t)B * T * 8;      // (T, 8, 8)

    riccati_kernel<<<1, 64>>>(F, G, H, Q, R, P0, Ps, T);
    wprep_kernel<<<C, 64>>>(Ps, T);
    wprep2_kernel<<<SC, 64>>>(C);
    {
        dim3 grid(C, GB);
        ends_kernel<<<grid, NB>>>(Y, B, T);
    }
    {
        dim3 grid(SC, GB);
        combineA_kernel<<<grid, NB>>>(B, C);
    }
    combineB_kernel<<<(B + 255) / 256, 256>>>(x0, B, SC);
    {
        dim3 grid(SC, GB);
        combineC_kernel<<<grid, NB>>>(B, C);
    }
    {
        dim3 grid(C, GB);
        scan_kernel<<<grid, NB>>>(Y, traj, B, T);
    }
}

// round 8
// speedup vs baseline: 1.3624x; 1.1136x over previous
#include <cuda_runtime.h>

// ---------------------------------------------------------------------------
// KF: batched square-root Kalman filter. B=2048, T=1000, n=d=8.
// Two-level chunked linear-scan: LCH=10 steps/chunk, SL=10 chunks/super.
// ends/scan: 64 threads/block, 2 batches per thread (amortized matrix LDS,
// 16 independent FMA chains per thread).
// ---------------------------------------------------------------------------

#define LCH  10
#define SL   10
#define TMAX 1024
#define CMAX ((TMAX + LCH - 1) / LCH)
#define SCMAX ((CMAX + SL - 1) / SL)
#define BMAX 2048
#define NB   128            // batches per block tile in ends/scan
#define NT   64             // threads per block in ends/scan (2 batches each)
#define SROW (LCH * 8 + 4)  // 84 floats = 21 float4 (odd) -> conflict-free LDS

__device__ __align__(16) float g_AK[TMAX * 128];   // per t: A[64], K[64] (t < tconv)
__device__ __align__(16) float g_W[TMAX * 64];     // per-step suffix weights
__device__ __align__(16) float g_Phi[CMAX * 64];   // chunk transitions
__device__ __align__(16) float g_W2[CMAX * 64];    // chunk-level suffix weights
__device__ __align__(16) float g_Psi[SCMAX * 64];  // super-chunk transitions
__device__ __align__(16) float g_E [(size_t)CMAX  * BMAX * 8];
__device__ __align__(16) float g_E2[(size_t)SCMAX * BMAX * 8];
__device__ __align__(16) float g_X [(size_t)CMAX  * BMAX * 8];
__device__ __align__(16) float g_X2[(size_t)SCMAX * BMAX * 8];
__device__ __align__(16) float g_frozen[192];      // A[64], K[64], P[64]
__device__ int   g_tconv;

// ============================ riccati ======================================

__global__ void __launch_bounds__(64) riccati_kernel(
    const float* __restrict__ Fg, const float* __restrict__ Gg,
    const float* __restrict__ Hg, const float* __restrict__ Qg,
    const float* __restrict__ Rg, const float* __restrict__ P0g,
    float* __restrict__ Ps_out, int T)
{
    __shared__ float sF[72], sHF[72], sGQG[72], sC1[72], sC2[72];
    __shared__ float sP[72], sU[72], sV[72], sPn[72], sT2[72], sS[72];
    __shared__ float sK[72], sTmp[72];
    __shared__ float sRed[4];
    __shared__ int   sFlag;

    const int tid = threadIdx.x;
    const int i = tid >> 3, j = tid & 7;
    const int ij = i * 9 + j;

    sF[ij] = Fg[tid]; sTmp[ij] = Gg[tid]; sU[ij] = Qg[tid];
    sC2[ij] = Rg[tid]; sP[ij] = P0g[tid]; sV[ij] = Hg[tid];
    if (tid == 0) sFlag = 0;
    __syncthreads();

    {   // GQ -> sPn ; HF -> sHF
        float a = 0.f, b = 0.f;
        #pragma unroll
        for (int k = 0; k < 8; k++) {
            a += sTmp[i*9+k] * sU[k*9+j];
            b += sV[i*9+k]   * sF[k*9+j];
        }
        sPn[ij] = a; sHF[ij] = b;
    }
    __syncthreads();
    {   // GQG = GQ * G^T
        float a = 0.f;
        #pragma unroll
        for (int k = 0; k < 8; k++) a += sPn[i*9+k] * sTmp[j*9+k];
        sGQG[ij] = a;
    }
    __syncthreads();
    {   // C1 = H * GQG
        float a = 0.f;
        #pragma unroll
        for (int k = 0; k < 8; k++) a += sV[i*9+k] * sGQG[k*9+j];
        sC1[ij] = a;
    }
    __syncthreads();
    {   // C2 = C1 * H^T + R
        float a = sC2[ij];
        #pragma unroll
        for (int k = 0; k < 8; k++) a += sC1[i*9+k] * sV[j*9+k];
        __syncthreads();
        sC2[ij] = a;
    }
    __syncthreads();

    int conv = 0;
    bool frozen = false;
    for (int t = 0; t < T; t++) {
        {   // U = F*P ; V = HF*P
            float a = 0.f, b = 0.f;
            #pragma unroll
            for (int k = 0; k < 8; k++) {
                float p = sP[k*9+j];
                a = fmaf(sF[i*9+k],  p, a);
                b = fmaf(sHF[i*9+k], p, b);
            }
            sU[ij] = a; sV[ij] = b;
        }
        __syncthreads();
        {   // Pn = U*F^T + GQG ; T2 = V*F^T + C1 ; S = V*HF^T + C2
            float pn = sGQG[ij], t2 = sC1[ij], s = sC2[ij];
            #pragma unroll
            for (int k = 0; k < 8; k++) {
                float fk = sF[j*9+k];
                float vk = sV[i*9+k];
                pn = fmaf(sU[i*9+k], fk, pn);
                t2 = fmaf(vk, fk, t2);
                s  = fmaf(vk, sHF[j*9+k], s);
            }
            sPn[ij] = pn; sT2[ij] = t2; sS[ij] = s;
        }
        __syncthreads();
        // Gauss-Jordan on [S | T2]: solves S X = T2 (S SPD, no pivoting).
        if (tid < 16) {
            float a[8];
            #pragma unroll
            for (int r = 0; r < 8; r++)
                a[r] = (tid < 8) ? sS[r*9+tid] : sT2[r*9+(tid-8)];
            #pragma unroll
            for (int p = 0; p < 8; p++) {
                float c[8];
                #pragma unroll
                for (int r = 0; r < 8; r++)
                    c[r] = __shfl_sync(0x0000FFFFu, a[r], p, 16);
                float pr = 1.0f / c[p];
                a[p] *= pr;
                #pragma unroll
                for (int r = 0; r < 8; r++)
                    if (r != p) a[r] = fmaf(-c[r], a[p], a[r]);
            }
            if (tid >= 8) {
                const int row = tid - 8;
                #pragma unroll
                for (int r = 0; r < 8; r++) sK[row*9 + r] = a[r];
            }
        }
        __syncthreads();
        // P+ = Pn - K*T2 ; A = F - K*HF
        float krow[8];
        #pragma unroll
        for (int k = 0; k < 8; k++) krow[k] = sK[i*9+k];
        float pp = sPn[ij], aa = sF[ij];
        #pragma unroll
        for (int k = 0; k < 8; k++) {
            pp = fmaf(-krow[k], sT2[k*9+j], pp);
            aa = fmaf(-krow[k], sHF[k*9+j], aa);
        }
        sTmp[ij] = pp;
        __syncthreads();
        float pnew = 0.5f * (pp + sTmp[j*9+i]);
        float pold = sP[ij];
        sP[ij] = pnew;

        Ps_out[(size_t)t*64 + tid]          = pnew;
        g_AK[(size_t)t*128 + i*8 + j]       = aa;
        g_AK[(size_t)t*128 + 64 + i*8 + j]  = krow[j];

        float dm = fabsf(pnew - pold);
        float pm = fabsf(pnew);
        #pragma unroll
        for (int o = 16; o > 0; o >>= 1) {
            dm = fmaxf(dm, __shfl_xor_sync(0xFFFFFFFFu, dm, o));
            pm = fmaxf(pm, __shfl_xor_sync(0xFFFFFFFFu, pm, o));
        }
        if ((tid & 31) == 0) { sRed[(tid>>5)*2] = dm; sRed[(tid>>5)*2+1] = pm; }
        __syncthreads();
        if (tid == 0) {
            float d = fmaxf(sRed[0], sRed[2]);
            float p = fmaxf(sRed[1], sRed[3]);
            if (t >= 12 && d < 2e-4f * p) conv++; else conv = 0;
            sFlag = (conv >= 2) ? 1 : 0;
        }
        __syncthreads();
        if (sFlag) {
            g_frozen[tid]       = aa;
            g_frozen[64 + tid]  = krow[j];
            g_frozen[128 + tid] = pnew;
            if (tid == 0) g_tconv = t + 1;
            frozen = true;
            break;
        }
    }
    if (!frozen && tid == 0) g_tconv = T;
}

// ======================= shared A/K staging helper =========================

__device__ __forceinline__ void load_sAK(float* sAK, int L0, int Lc, int tconv,
                                         int tid, int nthr)
{
    const float4* gAK4 = (const float4*)g_AK;
    const float4* frz4 = (const float4*)g_frozen;
    for (int e = tid; e < Lc * 32; e += nthr) {
        const int t = L0 + (e >> 5);
        const int q = e & 31;
        ((float4*)sAK)[e] = (t < tconv) ? gAK4[(size_t)t * 32 + q] : frz4[q];
    }
}

// ============================ wprep ========================================

__global__ void __launch_bounds__(64) wprep_kernel(float* __restrict__ Ps_out, int T)
{
    const int c  = blockIdx.x;
    const int L0 = c * LCH;
    const int Lc = min(LCH, T - L0);
    const int tconv = g_tconv;

    __shared__ __align__(16) float sAK[LCH * 128];
    __shared__ float sM[2][72];

    const int tid = threadIdx.x;
    const int i = tid >> 3, j = tid & 7;
    load_sAK(sAK, L0, Lc, tconv, tid, 64);
    sM[0][i*9+j] = (i == j) ? 1.f : 0.f;

    for (int t = max(L0, tconv); t < L0 + Lc; t++)
        Ps_out[(size_t)t*64 + tid] = g_frozen[128 + tid];
    __syncthreads();

    int pb = 0;
    for (int jj = Lc - 1; jj >= 0; jj--) {
        const float* a = sAK + jj * 128;
        float w = 0.f, m = 0.f;
        #pragma unroll
        for (int k = 0; k < 8; k++) {
            float mk = sM[pb][i*9+k];
            w = fmaf(mk, a[64 + k*8 + j], w);
            m = fmaf(mk, a[k*8 + j],      m);
        }
        g_W[(size_t)(L0 + jj)*64 + tid] = w;
        sM[pb ^ 1][i*9+j] = m;
        pb ^= 1;
        __syncthreads();
    }
    g_Phi[c*64 + tid] = sM[pb][i*9+j];
}

// ============================ wprep2 =======================================

__global__ void __launch_bounds__(64) wprep2_kernel(int C)
{
    const int s  = blockIdx.x;
    const int c0 = s * SL;
    const int nc = min(SL, C - c0);
    __shared__ float sM[2][72];
    __shared__ float sPhi[SL * 64];

    const int tid = threadIdx.x;
    const int i = tid >> 3, j = tid & 7;
    for (int e = tid; e < nc * 64; e += 64) sPhi[e] = g_Phi[c0 * 64 + e];
    sM[0][i*9+j] = (i == j) ? 1.f : 0.f;
    __syncthreads();

    int pb = 0;
    for (int jj = nc - 1; jj >= 0; jj--) {
        g_W2[(c0 + jj)*64 + tid] = sM[pb][i*9+j];
        const float* ph = sPhi + jj * 64;
        float m = 0.f;
        #pragma unroll
        for (int k = 0; k < 8; k++)
            m = fmaf(sM[pb][i*9+k], ph[k*8 + j], m);
        sM[pb ^ 1][i*9+j] = m;
        pb ^= 1;
        __syncthreads();
    }
    g_Psi[s*64 + tid] = sM[pb][i*9+j];
}

// ====================== Y tile staging helpers =============================

__device__ __forceinline__ void stage_Y_in(float* sY, const float* __restrict__ Y,
                                           int b0, int L0, int Lc, int B, int T,
                                           int tid, int nthr)
{
    const float4* Y4 = (const float4*)Y;
    for (int idx = tid; idx < NB * 2 * LCH; idx += nthr) {
        const int row = idx / (2 * LCH);
        const int col = idx - row * (2 * LCH);
        const int b = b0 + row;
        if (b < B && col < 2 * Lc)
            ((float4*)(sY + row * SROW))[col] = Y4[((size_t)b * T + L0) * 2 + col];
    }
}

__device__ __forceinline__ void stage_out(const float* sY, float* __restrict__ traj,
                                          int b0, int L0, int Lc, int B, int T,
                                          int tid, int nthr)
{
    float4* T4 = (float4*)traj;
    for (int idx = tid; idx < NB * 2 * LCH; idx += nthr) {
        const int row = idx / (2 * LCH);
        const int col = idx - row * (2 * LCH);
        const int b = b0 + row;
        if (b < B && col < 2 * Lc)
            T4[((size_t)b * T + L0) * 2 + col] = ((const float4*)(sY + row * SROW))[col];
    }
}

// ============================ ends =========================================
// 64 threads, each accumulating TWO batches against shared W.

__global__ void __launch_bounds__(NT) ends_kernel(
    const float* __restrict__ Y, int B, int T)
{
    const int c  = blockIdx.x;
    const int L0 = c * LCH;
    const int Lc = min(LCH, T - L0);

    __shared__ __align__(16) float sW[LCH * 64];
    __shared__ __align__(16) float sY[NB * SROW];

    const int tid = threadIdx.x;
    for (int e = tid; e < Lc * 16; e += NT)
        ((float4*)sW)[e] = ((const float4*)(g_W + (size_t)L0 * 64))[e];
    stage_Y_in(sY, Y, blockIdx.y * NB, L0, Lc, B, T, tid, NT);
    __syncthreads();

    const int bA = blockIdx.y * NB + tid;
    const int bB = bA + NT;
    const float4* yA = (const float4*)(sY + tid * SROW);
    const float4* yB = (const float4*)(sY + (tid + NT) * SROW);

    float accA[8], accB[8];
    #pragma unroll
    for (int i = 0; i < 8; i++) { accA[i] = 0.f; accB[i] = 0.f; }

    #pragma unroll
    for (int jj = 0; jj < LCH; jj++) {
        if (jj < Lc) {
            const float4 a0 = yA[2*jj], a1 = yA[2*jj + 1];
            const float4 b0 = yB[2*jj], b1 = yB[2*jj + 1];
            const float* w = sW + jj * 64;
            #pragma unroll
            for (int i = 0; i < 8; i++) {
                const float w0 = w[i*8+0], w1 = w[i*8+1], w2 = w[i*8+2], w3 = w[i*8+3];
                const float w4 = w[i*8+4], w5 = w[i*8+5], w6 = w[i*8+6], w7 = w[i*8+7];
                float sa = accA[i], sb = accB[i];
                sa = fmaf(w0, a0.x, sa);  sb = fmaf(w0, b0.x, sb);
                sa = fmaf(w1, a0.y, sa);  sb = fmaf(w1, b0.y, sb);
                sa = fmaf(w2, a0.z, sa);  sb = fmaf(w2, b0.z, sb);
                sa = fmaf(w3, a0.w, sa);  sb = fmaf(w3, b0.w, sb);
                sa = fmaf(w4, a1.x, sa);  sb = fmaf(w4, b1.x, sb);
                sa = fmaf(w5, a1.y, sa);  sb = fmaf(w5, b1.y, sb);
                sa = fmaf(w6, a1.z, sa);  sb = fmaf(w6, b1.z, sb);
                sa = fmaf(w7, a1.w, sa);  sb = fmaf(w7, b1.w, sb);
                accA[i] = sa; accB[i] = sb;
            }
        }
    }
    if (bA < B) {
        float4* eo = (float4*)(g_E + ((size_t)c * B + bA) * 8);
        eo[0] = make_float4(accA[0], accA[1], accA[2], accA[3]);
        eo[1] = make_float4(accA[4], accA[5], accA[6], accA[7]);
    }
    if (bB < B) {
        float4* eo = (float4*)(g_E + ((size_t)c * B + bB) * 8);
        eo[0] = make_float4(accB[0], accB[1], accB[2], accB[3]);
        eo[1] = make_float4(accB[4], accB[5], accB[6], accB[7]);
    }
}

// ============================ combineA =====================================

__global__ void __launch_bounds__(128) combineA_kernel(int B, int C)
{
    const int s  = blockIdx.x;
    const int c0 = s * SL;
    const int nc = min(SL, C - c0);

    __shared__ __align__(16) float sW2[SL * 64];
    const int tid = threadIdx.x;
    for (int e = tid; e < nc * 16; e += 128)
        ((float4*)sW2)[e] = ((const float4*)(g_W2 + c0 * 64))[e];
    __syncthreads();

    const int b = blockIdx.y * 128 + tid;
    const bool ok = (b < B);
    const int bs = ok ? b : 0;

    float acc[8];
    #pragma unroll
    for (int i = 0; i < 8; i++) acc[i] = 0.f;

    for (int jj = 0; jj < nc; jj++) {
        const float4* ep = (const float4*)(g_E + ((size_t)(c0 + jj) * B + bs) * 8);
        const float4 e0 = ep[0], e1 = ep[1];
        const float* w = sW2 + jj * 64;
        #pragma unroll
        for (int i = 0; i < 8; i++) {
            float a = acc[i];
            a = fmaf(w[i*8+0], e0.x, a); a = fmaf(w[i*8+1], e0.y, a);
            a = fmaf(w[i*8+2], e0.z, a); a = fmaf(w[i*8+3], e0.w, a);
            a = fmaf(w[i*8+4], e1.x, a); a = fmaf(w[i*8+5], e1.y, a);
            a = fmaf(w[i*8+6], e1.z, a); a = fmaf(w[i*8+7], e1.w, a);
            acc[i] = a;
        }
    }
    if (ok) {
        float4* eo = (float4*)(g_E2 + ((size_t)s * B + b) * 8);
        eo[0] = make_float4(acc[0], acc[1], acc[2], acc[3]);
        eo[1] = make_float4(acc[4], acc[5], acc[6], acc[7]);
    }
}

// ============================ combineB =====================================

__global__ void __launch_bounds__(256) combineB_kernel(
    const float* __restrict__ x0, int B, int SC)
{
    __shared__ float sPsi[SCMAX * 64];
    const int tid = threadIdx.x;
    for (int e = tid; e < SC * 64; e += 256) sPsi[e] = g_Psi[e];
    __syncthreads();

    const int b = blockIdx.x * 256 + tid;
    const bool ok = (b < B);
    const int bs = ok ? b : 0;

    float x[8];
    {
        const float4* xp = (const float4*)(x0 + bs * 8);
        float4 a = xp[0], b4 = xp[1];
        x[0]=a.x; x[1]=a.y; x[2]=a.z; x[3]=a.w;
        x[4]=b4.x; x[5]=b4.y; x[6]=b4.z; x[7]=b4.w;
    }

    for (int s = 0; s < SC; s++) {
        if (ok) {
            float4* xo = (float4*)(g_X2 + ((size_t)s * B + b) * 8);
            xo[0] = make_float4(x[0], x[1], x[2], x[3]);
            xo[1] = make_float4(x[4], x[5], x[6], x[7]);
        }
        const float4* ep = (const float4*)(g_E2 + ((size_t)s * B + bs) * 8);
        const float4 e0 = ep[0], e1 = ep[1];
        const float* pr = sPsi + s * 64;
        float xn[8];
        #pragma unroll
        for (int i = 0; i < 8; i++) {
            float a = 0.f;
            #pragma unroll
            for (int k = 0; k < 8; k++) a = fmaf(pr[i*8+k], x[k], a);
            xn[i] = a;
        }
        xn[0]+=e0.x; xn[1]+=e0.y; xn[2]+=e0.z; xn[3]+=e0.w;
        xn[4]+=e1.x; xn[5]+=e1.y; xn[6]+=e1.z; xn[7]+=e1.w;
        #pragma unroll
        for (int i = 0; i < 8; i++) x[i] = xn[i];
    }
}

// ============================ combineC =====================================

__global__ void __launch_bounds__(128) combineC_kernel(int B, int C)
{
    const int s  = blockIdx.x;
    const int c0 = s * SL;
    const int nc = min(SL, C - c0);

    __shared__ __align__(16) float sPhi[SL * 64];
    const int tid = threadIdx.x;
    for (int e = tid; e < nc * 16; e += 128)
        ((float4*)sPhi)[e] = ((const float4*)(g_Phi + c0 * 64))[e];
    __syncthreads();

    const int b = blockIdx.y * 128 + tid;
    const bool ok = (b < B);
    const int bs = ok ? b : 0;

    float x[8];
    {
        const float4* xp = (const float4*)(g_X2 + ((size_t)s * B + bs) * 8);
        float4 a = xp[0], b4 = xp[1];
        x[0]=a.x; x[1]=a.y; x[2]=a.z; x[3]=a.w;
        x[4]=b4.x; x[5]=b4.y; x[6]=b4.z; x[7]=b4.w;
    }

    for (int jj = 0; jj < nc; jj++) {
        const int c = c0 + jj;
        if (ok) {
            float4* xo = (float4*)(g_X + ((size_t)c * B + b) * 8);
            xo[0] = make_float4(x[0], x[1], x[2], x[3]);
            xo[1] = make_float4(x[4], x[5], x[6], x[7]);
        }
        if (jj < nc - 1) {
            const float4* ep = (const float4*)(g_E + ((size_t)c * B + bs) * 8);
            const float4 e0 = ep[0], e1 = ep[1];
            const float* pr = sPhi + jj * 64;
            float xn[8];
            #pragma unroll
            for (int i = 0; i < 8; i++) {
                float a = 0.f;
                #pragma unroll
                for (int k = 0; k < 8; k++) a = fmaf(pr[i*8+k], x[k], a);
                xn[i] = a;
            }
            xn[0]+=e0.x; xn[1]+=e0.y; xn[2]+=e0.z; xn[3]+=e0.w;
            xn[4]+=e1.x; xn[5]+=e1.y; xn[6]+=e1.z; xn[7]+=e1.w;
            #pragma unroll
            for (int i = 0; i < 8; i++) x[i] = xn[i];
        }
    }
}

// ============================ scan =========================================
// 64 threads, each carrying TWO recursion chains against shared A/K.

__global__ void __launch_bounds__(NT) scan_kernel(
    const float* __restrict__ Y, float* __restrict__ traj, int B, int T)
{
    const int c  = blockIdx.x;
    const int L0 = c * LCH;
    const int Lc = min(LCH, T - L0);
    const int tconv = g_tconv;

    __shared__ __align__(16) float sAK[LCH * 128];
    __shared__ __align__(16) float sY[NB * SROW];

    const int tid = threadIdx.x;
    load_sAK(sAK, L0, Lc, tconv, tid, NT);
    stage_Y_in(sY, Y, blockIdx.y * NB, L0, Lc, B, T, tid, NT);
    __syncthreads();

    const int bA = blockIdx.y * NB + tid;
    const int bsA = (bA < B) ? bA : 0;
    const int bB = bA + NT;
    const int bsB = (bB < B) ? bB : 0;
    float* yA = sY + tid * SROW;
    float* yB = sY + (tid + NT) * SROW;

    float xA[8], xB[8];
    {
        const float4* xp = (const float4*)(g_X + ((size_t)c * B + bsA) * 8);
        float4 a = xp[0], b4 = xp[1];
        xA[0]=a.x; xA[1]=a.y; xA[2]=a.z; xA[3]=a.w;
        xA[4]=b4.x; xA[5]=b4.y; xA[6]=b4.z; xA[7]=b4.w;
    }
    {
        const float4* xp = (const float4*)(g_X + ((size_t)c * B + bsB) * 8);
        float4 a = xp[0], b4 = xp[1];
        xB[0]=a.x; xB[1]=a.y; xB[2]=a.z; xB[3]=a.w;
        xB[4]=b4.x; xB[5]=b4.y; xB[6]=b4.z; xB[7]=b4.w;
    }

    #pragma unroll
    for (int jj = 0; jj < LCH; jj++) {
        if (jj < Lc) {
            const float4 ya0 = ((const float4*)yA)[2*jj];
            const float4 ya1 = ((const float4*)yA)[2*jj + 1];
            const float4 yb0 = ((const float4*)yB)[2*jj];
            const float4 yb1 = ((const float4*)yB)[2*jj + 1];
            const float* a = sAK + jj * 128;      // A [0..63], K [64..127]
            float xnA[8], xnB[8];
            #pragma unroll
            for (int i = 0; i < 8; i++) {
                const float* ar = a + i * 8;
                const float* kr = a + 64 + i * 8;
                const float a0 = ar[0], a1 = ar[1], a2 = ar[2], a3 = ar[3];
                const float a4 = ar[4], a5 = ar[5], a6 = ar[6], a7 = ar[7];
                const float k0 = kr[0], k1 = kr[1], k2 = kr[2], k3 = kr[3];
                const float k4 = kr[4], k5 = kr[5], k6 = kr[6], k7 = kr[7];
                float sA0 = a0 * xA[0];
                float sA1 = k0 * ya0.x;
                float sB0 = a0 * xB[0];
                float sB1 = k0 * yb0.x;
                sA0 = fmaf(a1, xA[1], sA0);  sB0 = fmaf(a1, xB[1], sB0);
                sA1 = fmaf(k1, ya0.y, sA1);  sB1 = fmaf(k1, yb0.y, sB1);
                sA0 = fmaf(a2, xA[2], sA0);  sB0 = fmaf(a2, xB[2], sB0);
                sA1 = fmaf(k2, ya0.z, sA1);  sB1 = fmaf(k2, yb0.z, sB1);
                sA0 = fmaf(a3, xA[3], sA0);  sB0 = fmaf(a3, xB[3], sB0);
                sA1 = fmaf(k3, ya0.w, sA1);  sB1 = fmaf(k3, yb0.w, sB1);
                sA0 = fmaf(a4, xA[4], sA0);  sB0 = fmaf(a4, xB[4], sB0);
                sA1 = fmaf(k4, ya1.x, sA1);  sB1 = fmaf(k4, yb1.x, sB1);
                sA0 = fmaf(a5, xA[5], sA0);  sB0 = fmaf(a5, xB[5], sB0);
                sA1 = fmaf(k5, ya1.y, sA1);  sB1 = fmaf(k5, yb1.y, sB1);
                sA0 = fmaf(a6, xA[6], sA0);  sB0 = fmaf(a6, xB[6], sB0);
                sA1 = fmaf(k6, ya1.z, sA1);  sB1 = fmaf(k6, yb1.z, sB1);
                sA0 = fmaf(a7, xA[7], sA0);  sB0 = fmaf(a7, xB[7], sB0);
                sA1 = fmaf(k7, ya1.w, sA1);  sB1 = fmaf(k7, yb1.w, sB1);
                xnA[i] = sA0 + sA1;
                xnB[i] = sB0 + sB1;
            }
            #pragma unroll
            for (int i = 0; i < 8; i++) { xA[i] = xnA[i]; xB[i] = xnB[i]; }
            ((float4*)yA)[2*jj]     = make_float4(xA[0], xA[1], xA[2], xA[3]);
            ((float4*)yA)[2*jj + 1] = make_float4(xA[4], xA[5], xA[6], xA[7]);
            ((float4*)yB)[2*jj]     = make_float4(xB[0], xB[1], xB[2], xB[3]);
            ((float4*)yB)[2*jj + 1] = make_float4(xB[4], xB[5], xB[6], xB[7]);
        }
    }
    __syncthreads();
    stage_out(sY, traj, blockIdx.y * NB, L0, Lc, B, T, tid, NT);
}

// ============================ launch =======================================

extern "C" void kernel_launch(void* const* d_in, const int* in_sizes, int n_in,
                              void* d_out, int out_size)
{
    const float* Y  = (const float*)d_in[0];
    const float* F  = (const float*)d_in[1];
    const float* G  = (const float*)d_in[2];
    const float* H  = (const float*)d_in[3];
    const float* Q  = (const float*)d_in[4];
    const float* R  = (const float*)d_in[5];
    const float* x0 = (const float*)d_in[6];
    const float* P0 = (const float*)d_in[7];

    const int B  = in_sizes[6] / 8;
    const int T  = in_sizes[0] / (B * 8);
    const int C  = (T + LCH - 1) / LCH;
    const int SC = (C + SL - 1) / SL;
    const int GB = (B + NB - 1) / NB;

    float* traj = (float*)d_out;                 // (B, T, 8)
    float* Ps   = traj + (size_t)B * T * 8;      // (T, 8, 8)

    riccati_kernel<<<1, 64>>>(F, G, H, Q, R, P0, Ps, T);
    wprep_kernel<<<C, 64>>>(Ps, T);
    wprep2_kernel<<<SC, 64>>>(C);
    {
        dim3 grid(C, GB);
        ends_kernel<<<grid, NT>>>(Y, B, T);
    }
    {
        dim3 grid(SC, (B + 127) / 128);
        combineA_kernel<<<grid, 128>>>(B, C);
    }
    combineB_kernel<<<(B + 255) / 256, 256>>>(x0, B, SC);
    {
        dim3 grid(SC, (B + 127) / 128);
        combineC_kernel<<<grid, 128>>>(B, C);
    }
    {
        dim3 grid(C, GB);
        scan_kernel<<<grid, NT>>>(Y, traj, B, T);
    }
}

// round 10
// speedup vs baseline: 1.5368x; 1.1280x over previous
#include <cuda_runtime.h>

// ---------------------------------------------------------------------------
// KF: batched square-root Kalman filter. B=2048, T=1000, n=d=8.
// Two-level chunked linear-scan: LCH=10 steps/chunk, SL=10 chunks/super.
// ends: direct-global Y reads, 2 batches/thread, tiny smem (occupancy).
// scan: direct-global Y reads, coalesced staged output, 2 chains/thread.
// ---------------------------------------------------------------------------

#define LCH  10
#define SL   10
#define TMAX 1024
#define CMAX ((TMAX + LCH - 1) / LCH)
#define SCMAX ((CMAX + SL - 1) / SL)
#define BMAX 2048
#define NB   128            // batches per block tile in scan
#define NT   64             // threads per block in scan (2 batches each)
#define SROW (LCH * 8 + 4)  // 84 floats = 21 float4 (odd) -> conflict-free LDS

__device__ __align__(16) float g_AK[TMAX * 128];   // per t: A[64], K[64] (t < tconv)
__device__ __align__(16) float g_W[TMAX * 64];     // per-step suffix weights
__device__ __align__(16) float g_Phi[CMAX * 64];   // chunk transitions
__device__ __align__(16) float g_W2[CMAX * 64];    // chunk-level suffix weights
__device__ __align__(16) float g_Psi[SCMAX * 64];  // super-chunk transitions
__device__ __align__(16) float g_E [(size_t)CMAX  * BMAX * 8];
__device__ __align__(16) float g_E2[(size_t)SCMAX * BMAX * 8];
__device__ __align__(16) float g_X [(size_t)CMAX  * BMAX * 8];
__device__ __align__(16) float g_X2[(size_t)SCMAX * BMAX * 8];
__device__ __align__(16) float g_frozen[192];      // A[64], K[64], P[64]
__device__ int   g_tconv;

// ============================ riccati ======================================

__global__ void __launch_bounds__(64) riccati_kernel(
    const float* __restrict__ Fg, const float* __restrict__ Gg,
    const float* __restrict__ Hg, const float* __restrict__ Qg,
    const float* __restrict__ Rg, const float* __restrict__ P0g,
    float* __restrict__ Ps_out, int T)
{
    __shared__ float sF[72], sHF[72], sGQG[72], sC1[72], sC2[72];
    __shared__ float sP[72], sU[72], sV[72], sPn[72], sT2[72], sS[72];
    __shared__ float sK[72], sTmp[72];
    __shared__ float sRed[4];
    __shared__ int   sFlag;

    const int tid = threadIdx.x;
    const int i = tid >> 3, j = tid & 7;
    const int ij = i * 9 + j;

    sF[ij] = Fg[tid]; sTmp[ij] = Gg[tid]; sU[ij] = Qg[tid];
    sC2[ij] = Rg[tid]; sP[ij] = P0g[tid]; sV[ij] = Hg[tid];
    if (tid == 0) sFlag = 0;
    __syncthreads();

    {   // GQ -> sPn ; HF -> sHF
        float a = 0.f, b = 0.f;
        #pragma unroll
        for (int k = 0; k < 8; k++) {
            a += sTmp[i*9+k] * sU[k*9+j];
            b += sV[i*9+k]   * sF[k*9+j];
        }
        sPn[ij] = a; sHF[ij] = b;
    }
    __syncthreads();
    {   // GQG = GQ * G^T
        float a = 0.f;
        #pragma unroll
        for (int k = 0; k < 8; k++) a += sPn[i*9+k] * sTmp[j*9+k];
        sGQG[ij] = a;
    }
    __syncthreads();
    {   // C1 = H * GQG
        float a = 0.f;
        #pragma unroll
        for (int k = 0; k < 8; k++) a += sV[i*9+k] * sGQG[k*9+j];
        sC1[ij] = a;
    }
    __syncthreads();
    {   // C2 = C1 * H^T + R
        float a = sC2[ij];
        #pragma unroll
        for (int k = 0; k < 8; k++) a += sC1[i*9+k] * sV[j*9+k];
        __syncthreads();
        sC2[ij] = a;
    }
    __syncthreads();

    int conv = 0;
    bool frozen = false;
    for (int t = 0; t < T; t++) {
        {   // U = F*P ; V = HF*P
            float a = 0.f, b = 0.f;
            #pragma unroll
            for (int k = 0; k < 8; k++) {
                float p = sP[k*9+j];
                a = fmaf(sF[i*9+k],  p, a);
                b = fmaf(sHF[i*9+k], p, b);
            }
            sU[ij] = a; sV[ij] = b;
        }
        __syncthreads();
        {   // Pn = U*F^T + GQG ; T2 = V*F^T + C1 ; S = V*HF^T + C2
            float pn = sGQG[ij], t2 = sC1[ij], s = sC2[ij];
            #pragma unroll
            for (int k = 0; k < 8; k++) {
                float fk = sF[j*9+k];
                float vk = sV[i*9+k];
                pn = fmaf(sU[i*9+k], fk, pn);
                t2 = fmaf(vk, fk, t2);
                s  = fmaf(vk, sHF[j*9+k], s);
            }
            sPn[ij] = pn; sT2[ij] = t2; sS[ij] = s;
        }
        __syncthreads();
        // Gauss-Jordan on [S | T2]: solves S X = T2 (S SPD, no pivoting).
        if (tid < 16) {
            float a[8];
            #pragma unroll
            for (int r = 0; r < 8; r++)
                a[r] = (tid < 8) ? sS[r*9+tid] : sT2[r*9+(tid-8)];
            #pragma unroll
            for (int p = 0; p < 8; p++) {
                float c[8];
                #pragma unroll
                for (int r = 0; r < 8; r++)
                    c[r] = __shfl_sync(0x0000FFFFu, a[r], p, 16);
                float pr = 1.0f / c[p];
                a[p] *= pr;
                #pragma unroll
                for (int r = 0; r < 8; r++)
                    if (r != p) a[r] = fmaf(-c[r], a[p], a[r]);
            }
            if (tid >= 8) {
                const int row = tid - 8;
                #pragma unroll
                for (int r = 0; r < 8; r++) sK[row*9 + r] = a[r];
            }
        }
        __syncthreads();
        // P+ = Pn - K*T2 ; A = F - K*HF
        float krow[8];
        #pragma unroll
        for (int k = 0; k < 8; k++) krow[k] = sK[i*9+k];
        float pp = sPn[ij], aa = sF[ij];
        #pragma unroll
        for (int k = 0; k < 8; k++) {
            pp = fmaf(-krow[k], sT2[k*9+j], pp);
            aa = fmaf(-krow[k], sHF[k*9+j], aa);
        }
        sTmp[ij] = pp;
        __syncthreads();
        float pnew = 0.5f * (pp + sTmp[j*9+i]);
        float pold = sP[ij];
        sP[ij] = pnew;

        Ps_out[(size_t)t*64 + tid]          = pnew;
        g_AK[(size_t)t*128 + i*8 + j]       = aa;
        g_AK[(size_t)t*128 + 64 + i*8 + j]  = krow[j];

        float dm = fabsf(pnew - pold);
        float pm = fabsf(pnew);
        #pragma unroll
        for (int o = 16; o > 0; o >>= 1) {
            dm = fmaxf(dm, __shfl_xor_sync(0xFFFFFFFFu, dm, o));
            pm = fmaxf(pm, __shfl_xor_sync(0xFFFFFFFFu, pm, o));
        }
        if ((tid & 31) == 0) { sRed[(tid>>5)*2] = dm; sRed[(tid>>5)*2+1] = pm; }
        __syncthreads();
        if (tid == 0) {
            float d = fmaxf(sRed[0], sRed[2]);
            float p = fmaxf(sRed[1], sRed[3]);
            if (t >= 12 && d < 2e-4f * p) conv++; else conv = 0;
            sFlag = (conv >= 2) ? 1 : 0;
        }
        __syncthreads();
        if (sFlag) {
            g_frozen[tid]       = aa;
            g_frozen[64 + tid]  = krow[j];
            g_frozen[128 + tid] = pnew;
            if (tid == 0) g_tconv = t + 1;
            frozen = true;
            break;
        }
    }
    if (!frozen && tid == 0) g_tconv = T;
}

// ======================= shared A/K staging helper =========================

__device__ __forceinline__ void load_sAK(float* sAK, int L0, int Lc, int tconv,
                                         int tid, int nthr)
{
    const float4* gAK4 = (const float4*)g_AK;
    const float4* frz4 = (const float4*)g_frozen;
    for (int e = tid; e < Lc * 32; e += nthr) {
        const int t = L0 + (e >> 5);
        const int q = e & 31;
        ((float4*)sAK)[e] = (t < tconv) ? gAK4[(size_t)t * 32 + q] : frz4[q];
    }
}

// ============================ wprep ========================================

__global__ void __launch_bounds__(64) wprep_kernel(float* __restrict__ Ps_out, int T)
{
    const int c  = blockIdx.x;
    const int L0 = c * LCH;
    const int Lc = min(LCH, T - L0);
    const int tconv = g_tconv;

    __shared__ __align__(16) float sAK[LCH * 128];
    __shared__ float sM[2][72];

    const int tid = threadIdx.x;
    const int i = tid >> 3, j = tid & 7;
    load_sAK(sAK, L0, Lc, tconv, tid, 64);
    sM[0][i*9+j] = (i == j) ? 1.f : 0.f;

    for (int t = max(L0, tconv); t < L0 + Lc; t++)
        Ps_out[(size_t)t*64 + tid] = g_frozen[128 + tid];
    __syncthreads();

    int pb = 0;
    for (int jj = Lc - 1; jj >= 0; jj--) {
        const float* a = sAK + jj * 128;
        float w = 0.f, m = 0.f;
        #pragma unroll
        for (int k = 0; k < 8; k++) {
            float mk = sM[pb][i*9+k];
            w = fmaf(mk, a[64 + k*8 + j], w);
            m = fmaf(mk, a[k*8 + j],      m);
        }
        g_W[(size_t)(L0 + jj)*64 + tid] = w;
        sM[pb ^ 1][i*9+j] = m;
        pb ^= 1;
        __syncthreads();
    }
    g_Phi[c*64 + tid] = sM[pb][i*9+j];
}

// ============================ wprep2 =======================================

__global__ void __launch_bounds__(64) wprep2_kernel(int C)
{
    const int s  = blockIdx.x;
    const int c0 = s * SL;
    const int nc = min(SL, C - c0);
    __shared__ float sM[2][72];
    __shared__ float sPhi[SL * 64];

    const int tid = threadIdx.x;
    const int i = tid >> 3, j = tid & 7;
    for (int e = tid; e < nc * 64; e += 64) sPhi[e] = g_Phi[c0 * 64 + e];
    sM[0][i*9+j] = (i == j) ? 1.f : 0.f;
    __syncthreads();

    int pb = 0;
    for (int jj = nc - 1; jj >= 0; jj--) {
        g_W2[(c0 + jj)*64 + tid] = sM[pb][i*9+j];
        const float* ph = sPhi + jj * 64;
        float m = 0.f;
        #pragma unroll
        for (int k = 0; k < 8; k++)
            m = fmaf(sM[pb][i*9+k], ph[k*8 + j], m);
        sM[pb ^ 1][i*9+j] = m;
        pb ^= 1;
        __syncthreads();
    }
    g_Psi[s*64 + tid] = sM[pb][i*9+j];
}

// ============================ ends =========================================
// Direct global Y reads (each thread streams contiguous 320B per batch),
// 2 batches per thread, 128 threads (256 batches/block), smem = sW only.

__global__ void __launch_bounds__(128) ends_kernel(
    const float* __restrict__ Y, int B, int T)
{
    const int c  = blockIdx.x;
    const int L0 = c * LCH;
    const int Lc = min(LCH, T - L0);

    __shared__ __align__(16) float sW[LCH * 64];
    const int tid = threadIdx.x;
    for (int e = tid; e < Lc * 16; e += 128)
        ((float4*)sW)[e] = ((const float4*)(g_W + (size_t)L0 * 64))[e];
    __syncthreads();

    const int bA = blockIdx.y * 256 + tid;
    const int bB = bA + 128;
    const int bsA = (bA < B) ? bA : 0;
    const int bsB = (bB < B) ? bB : 0;
    const float4* yA = (const float4*)(Y + ((size_t)bsA * T + L0) * 8);
    const float4* yB = (const float4*)(Y + ((size_t)bsB * T + L0) * 8);

    float accA[8], accB[8];
    #pragma unroll
    for (int i = 0; i < 8; i++) { accA[i] = 0.f; accB[i] = 0.f; }

    #pragma unroll
    for (int jj = 0; jj < LCH; jj++) {
        if (jj < Lc) {
            const float4 a0 = yA[2*jj], a1 = yA[2*jj + 1];
            const float4 b0 = yB[2*jj], b1 = yB[2*jj + 1];
            const float* w = sW + jj * 64;
            #pragma unroll
            for (int i = 0; i < 8; i++) {
                const float w0 = w[i*8+0], w1 = w[i*8+1], w2 = w[i*8+2], w3 = w[i*8+3];
                const float w4 = w[i*8+4], w5 = w[i*8+5], w6 = w[i*8+6], w7 = w[i*8+7];
                float sa = accA[i], sb = accB[i];
                sa = fmaf(w0, a0.x, sa);  sb = fmaf(w0, b0.x, sb);
                sa = fmaf(w1, a0.y, sa);  sb = fmaf(w1, b0.y, sb);
                sa = fmaf(w2, a0.z, sa);  sb = fmaf(w2, b0.z, sb);
                sa = fmaf(w3, a0.w, sa);  sb = fmaf(w3, b0.w, sb);
                sa = fmaf(w4, a1.x, sa);  sb = fmaf(w4, b1.x, sb);
                sa = fmaf(w5, a1.y, sa);  sb = fmaf(w5, b1.y, sb);
                sa = fmaf(w6, a1.z, sa);  sb = fmaf(w6, b1.z, sb);
                sa = fmaf(w7, a1.w, sa);  sb = fmaf(w7, b1.w, sb);
                accA[i] = sa; accB[i] = sb;
            }
        }
    }
    if (bA < B) {
        float4* eo = (float4*)(g_E + ((size_t)c * B + bA) * 8);
        eo[0] = make_float4(accA[0], accA[1], accA[2], accA[3]);
        eo[1] = make_float4(accA[4], accA[5], accA[6], accA[7]);
    }
    if (bB < B) {
        float4* eo = (float4*)(g_E + ((size_t)c * B + bB) * 8);
        eo[0] = make_float4(accB[0], accB[1], accB[2], accB[3]);
        eo[1] = make_float4(accB[4], accB[5], accB[6], accB[7]);
    }
}

// ============================ combineA =====================================

__global__ void __launch_bounds__(128) combineA_kernel(int B, int C)
{
    const int s  = blockIdx.x;
    const int c0 = s * SL;
    const int nc = min(SL, C - c0);

    __shared__ __align__(16) float sW2[SL * 64];
    const int tid = threadIdx.x;
    for (int e = tid; e < nc * 16; e += 128)
        ((float4*)sW2)[e] = ((const float4*)(g_W2 + c0 * 64))[e];
    __syncthreads();

    const int b = blockIdx.y * 128 + tid;
    const bool ok = (b < B);
    const int bs = ok ? b : 0;

    float acc[8];
    #pragma unroll
    for (int i = 0; i < 8; i++) acc[i] = 0.f;

    for (int jj = 0; jj < nc; jj++) {
        const float4* ep = (const float4*)(g_E + ((size_t)(c0 + jj) * B + bs) * 8);
        const float4 e0 = ep[0], e1 = ep[1];
        const float* w = sW2 + jj * 64;
        #pragma unroll
        for (int i = 0; i < 8; i++) {
            float a = acc[i];
            a = fmaf(w[i*8+0], e0.x, a); a = fmaf(w[i*8+1], e0.y, a);
            a = fmaf(w[i*8+2], e0.z, a); a = fmaf(w[i*8+3], e0.w, a);
            a = fmaf(w[i*8+4], e1.x, a); a = fmaf(w[i*8+5], e1.y, a);
            a = fmaf(w[i*8+6], e1.z, a); a = fmaf(w[i*8+7], e1.w, a);
            acc[i] = a;
        }
    }
    if (ok) {
        float4* eo = (float4*)(g_E2 + ((size_t)s * B + b) * 8);
        eo[0] = make_float4(acc[0], acc[1], acc[2], acc[3]);
        eo[1] = make_float4(acc[4], acc[5], acc[6], acc[7]);
    }
}

// ============================ combineB =====================================

__global__ void __launch_bounds__(256) combineB_kernel(
    const float* __restrict__ x0, int B, int SC)
{
    __shared__ float sPsi[SCMAX * 64];
    const int tid = threadIdx.x;
    for (int e = tid; e < SC * 64; e += 256) sPsi[e] = g_Psi[e];
    __syncthreads();

    const int b = blockIdx.x * 256 + tid;
    const bool ok = (b < B);
    const int bs = ok ? b : 0;

    float x[8];
    {
        const float4* xp = (const float4*)(x0 + bs * 8);
        float4 a = xp[0], b4 = xp[1];
        x[0]=a.x; x[1]=a.y; x[2]=a.z; x[3]=a.w;
        x[4]=b4.x; x[5]=b4.y; x[6]=b4.z; x[7]=b4.w;
    }

    for (int s = 0; s < SC; s++) {
        if (ok) {
            float4* xo = (float4*)(g_X2 + ((size_t)s * B + b) * 8);
            xo[0] = make_float4(x[0], x[1], x[2], x[3]);
            xo[1] = make_float4(x[4], x[5], x[6], x[7]);
        }
        const float4* ep = (const float4*)(g_E2 + ((size_t)s * B + bs) * 8);
        const float4 e0 = ep[0], e1 = ep[1];
        const float* pr = sPsi + s * 64;
        float xn[8];
        #pragma unroll
        for (int i = 0; i < 8; i++) {
            float a = 0.f;
            #pragma unroll
            for (int k = 0; k < 8; k++) a = fmaf(pr[i*8+k], x[k], a);
            xn[i] = a;
        }
        xn[0]+=e0.x; xn[1]+=e0.y; xn[2]+=e0.z; xn[3]+=e0.w;
        xn[4]+=e1.x; xn[5]+=e1.y; xn[6]+=e1.z; xn[7]+=e1.w;
        #pragma unroll
        for (int i = 0; i < 8; i++) x[i] = xn[i];
    }
}

// ============================ combineC =====================================

__global__ void __launch_bounds__(128) combineC_kernel(int B, int C)
{
    const int s  = blockIdx.x;
    const int c0 = s * SL;
    const int nc = min(SL, C - c0);

    __shared__ __align__(16) float sPhi[SL * 64];
    const int tid = threadIdx.x;
    for (int e = tid; e < nc * 16; e += 128)
        ((float4*)sPhi)[e] = ((const float4*)(g_Phi + c0 * 64))[e];
    __syncthreads();

    const int b = blockIdx.y * 128 + tid;
    const bool ok = (b < B);
    const int bs = ok ? b : 0;

    float x[8];
    {
        const float4* xp = (const float4*)(g_X2 + ((size_t)s * B + bs) * 8);
        float4 a = xp[0], b4 = xp[1];
        x[0]=a.x; x[1]=a.y; x[2]=a.z; x[3]=a.w;
        x[4]=b4.x; x[5]=b4.y; x[6]=b4.z; x[7]=b4.w;
    }

    for (int jj = 0; jj < nc; jj++) {
        const int c = c0 + jj;
        if (ok) {
            float4* xo = (float4*)(g_X + ((size_t)c * B + b) * 8);
            xo[0] = make_float4(x[0], x[1], x[2], x[3]);
            xo[1] = make_float4(x[4], x[5], x[6], x[7]);
        }
        if (jj < nc - 1) {
            const float4* ep = (const float4*)(g_E + ((size_t)c * B + bs) * 8);
            const float4 e0 = ep[0], e1 = ep[1];
            const float* pr = sPhi + jj * 64;
            float xn[8];
            #pragma unroll
            for (int i = 0; i < 8; i++) {
                float a = 0.f;
                #pragma unroll
                for (int k = 0; k < 8; k++) a = fmaf(pr[i*8+k], x[k], a);
                xn[i] = a;
            }
            xn[0]+=e0.x; xn[1]+=e0.y; xn[2]+=e0.z; xn[3]+=e0.w;
            xn[4]+=e1.x; xn[5]+=e1.y; xn[6]+=e1.z; xn[7]+=e1.w;
            #pragma unroll
            for (int i = 0; i < 8; i++) x[i] = xn[i];
        }
    }
}

// ============================ scan =========================================
// 2 chains/thread; Y read direct from global (contiguous per thread),
// outputs staged through shared and written coalesced.

__global__ void __launch_bounds__(NT) scan_kernel(
    const float* __restrict__ Y, float* __restrict__ traj, int B, int T)
{
    const int c  = blockIdx.x;
    const int L0 = c * LCH;
    const int Lc = min(LCH, T - L0);
    const int tconv = g_tconv;

    __shared__ __align__(16) float sAK[LCH * 128];
    __shared__ __align__(16) float sOut[NB * SROW];

    const int tid = threadIdx.x;
    load_sAK(sAK, L0, Lc, tconv, tid, NT);

    const int bA = blockIdx.y * NB + tid;
    const int bsA = (bA < B) ? bA : 0;
    const int bB = bA + NT;
    const int bsB = (bB < B) ? bB : 0;
    const float4* yA = (const float4*)(Y + ((size_t)bsA * T + L0) * 8);
    const float4* yB = (const float4*)(Y + ((size_t)bsB * T + L0) * 8);
    float* oA = sOut + tid * SROW;
    float* oB = sOut + (tid + NT) * SROW;

    float xA[8], xB[8];
    {
        const float4* xp = (const float4*)(g_X + ((size_t)c * B + bsA) * 8);
        float4 a = xp[0], b4 = xp[1];
        xA[0]=a.x; xA[1]=a.y; xA[2]=a.z; xA[3]=a.w;
        xA[4]=b4.x; xA[5]=b4.y; xA[6]=b4.z; xA[7]=b4.w;
    }
    {
        const float4* xp = (const float4*)(g_X + ((size_t)c * B + bsB) * 8);
        float4 a = xp[0], b4 = xp[1];
        xB[0]=a.x; xB[1]=a.y; xB[2]=a.z; xB[3]=a.w;
        xB[4]=b4.x; xB[5]=b4.y; xB[6]=b4.z; xB[7]=b4.w;
    }
    __syncthreads();   // sAK ready

    #pragma unroll
    for (int jj = 0; jj < LCH; jj++) {
        if (jj < Lc) {
            const float4 ya0 = yA[2*jj], ya1 = yA[2*jj + 1];
            const float4 yb0 = yB[2*jj], yb1 = yB[2*jj + 1];
            const float* a = sAK + jj * 128;      // A [0..63], K [64..127]
            float xnA[8], xnB[8];
            #pragma unroll
            for (int i = 0; i < 8; i++) {
                const float* ar = a + i * 8;
                const float* kr = a + 64 + i * 8;
                const float a0 = ar[0], a1 = ar[1], a2 = ar[2], a3 = ar[3];
                const float a4 = ar[4], a5 = ar[5], a6 = ar[6], a7 = ar[7];
                const float k0 = kr[0], k1 = kr[1], k2 = kr[2], k3 = kr[3];
                const float k4 = kr[4], k5 = kr[5], k6 = kr[6], k7 = kr[7];
                float sA0 = a0 * xA[0];
                float sA1 = k0 * ya0.x;
                float sB0 = a0 * xB[0];
                float sB1 = k0 * yb0.x;
                sA0 = fmaf(a1, xA[1], sA0);  sB0 = fmaf(a1, xB[1], sB0);
                sA1 = fmaf(k1, ya0.y, sA1);  sB1 = fmaf(k1, yb0.y, sB1);
                sA0 = fmaf(a2, xA[2], sA0);  sB0 = fmaf(a2, xB[2], sB0);
                sA1 = fmaf(k2, ya0.z, sA1);  sB1 = fmaf(k2, yb0.z, sB1);
                sA0 = fmaf(a3, xA[3], sA0);  sB0 = fmaf(a3, xB[3], sB0);
                sA1 = fmaf(k3, ya0.w, sA1);  sB1 = fmaf(k3, yb0.w, sB1);
                sA0 = fmaf(a4, xA[4], sA0);  sB0 = fmaf(a4, xB[4], sB0);
                sA1 = fmaf(k4, ya1.x, sA1);  sB1 = fmaf(k4, yb1.x, sB1);
                sA0 = fmaf(a5, xA[5], sA0);  sB0 = fmaf(a5, xB[5], sB0);
                sA1 = fmaf(k5, ya1.y, sA1);  sB1 = fmaf(k5, yb1.y, sB1);
                sA0 = fmaf(a6, xA[6], sA0);  sB0 = fmaf(a6, xB[6], sB0);
                sA1 = fmaf(k6, ya1.z, sA1);  sB1 = fmaf(k6, yb1.z, sB1);
                sA0 = fmaf(a7, xA[7], sA0);  sB0 = fmaf(a7, xB[7], sB0);
                sA1 = fmaf(k7, ya1.w, sA1);  sB1 = fmaf(k7, yb1.w, sB1);
                xnA[i] = sA0 + sA1;
                xnB[i] = sB0 + sB1;
            }
            #pragma unroll
            for (int i = 0; i < 8; i++) { xA[i] = xnA[i]; xB[i] = xnB[i]; }
            ((float4*)oA)[2*jj]     = make_float4(xA[0], xA[1], xA[2], xA[3]);
            ((float4*)oA)[2*jj + 1] = make_float4(xA[4], xA[5], xA[6], xA[7]);
            ((float4*)oB)[2*jj]     = make_float4(xB[0], xB[1], xB[2], xB[3]);
            ((float4*)oB)[2*jj + 1] = make_float4(xB[4], xB[5], xB[6], xB[7]);
        }
    }
    __syncthreads();

    // coalesced store of the output tile
    {
        float4* T4 = (float4*)traj;
        const int b0 = blockIdx.y * NB;
        for (int idx = tid; idx < NB * 2 * LCH; idx += NT) {
            const int row = idx / (2 * LCH);
            const int col = idx - row * (2 * LCH);
            const int b = b0 + row;
            if (b < B && col < 2 * Lc)
                T4[((size_t)b * T + L0) * 2 + col] =
                    ((const float4*)(sOut + row * SROW))[col];
        }
    }
}

// ============================ launch =======================================

extern "C" void kernel_launch(void* const* d_in, const int* in_sizes, int n_in,
                              void* d_out, int out_size)
{
    const float* Y  = (const float*)d_in[0];
    const float* F  = (const float*)d_in[1];
    const float* G  = (const float*)d_in[2];
    const float* H  = (const float*)d_in[3];
    const float* Q  = (const float*)d_in[4];
    const float* R  = (const float*)d_in[5];
    const float* x0 = (const float*)d_in[6];
    const float* P0 = (const float*)d_in[7];

    const int B  = in_sizes[6] / 8;
    const int T  = in_sizes[0] / (B * 8);
    const int C  = (T + LCH - 1) / LCH;
    const int SC = (C + SL - 1) / SL;

    float* traj = (float*)d_out;                 // (B, T, 8)
    float* Ps   = traj + (size_t)B * T * 8;      // (T, 8, 8)

    riccati_kernel<<<1, 64>>>(F, G, H, Q, R, P0, Ps, T);
    wprep_kernel<<<C, 64>>>(Ps, T);
    wprep2_kernel<<<SC, 64>>>(C);
    {
        dim3 grid(C, (B + 255) / 256);
        ends_kernel<<<grid, 128>>>(Y, B, T);
    }
    {
        dim3 grid(SC, (B + 127) / 128);
        combineA_kernel<<<grid, 128>>>(B, C);
    }
    combineB_kernel<<<(B + 255) / 256, 256>>>(x0, B, SC);
    {
        dim3 grid(SC, (B + 127) / 128);
        combineC_kernel<<<grid, 128>>>(B, C);
    }
    {
        dim3 grid(C, (B + NB - 1) / NB);
        scan_kernel<<<grid, NT>>>(Y, traj, B, T);
    }
}

// round 11
// speedup vs baseline: 1.5371x; 1.0002x over previous
#include <cuda_runtime.h>

// ---------------------------------------------------------------------------
// KF: batched square-root Kalman filter. B=2048, T=1000, n=d=8.
// Two-level chunked linear-scan: LCH=10 steps/chunk, SL=10 chunks/super.
// ends/scan: branch-free fast path (Lc==LCH) so all y LDGs hoist (high MLP).
// ---------------------------------------------------------------------------

#define LCH  10
#define SL   10
#define TMAX 1024
#define CMAX ((TMAX + LCH - 1) / LCH)
#define SCMAX ((CMAX + SL - 1) / SL)
#define BMAX 2048
#define NB   128            // batches per block tile in scan
#define NT   64             // threads per block in scan (2 batches each)
#define SROW (LCH * 8 + 4)  // 84 floats = 21 float4 (odd) -> conflict-free LDS

__device__ __align__(16) float g_AK[TMAX * 128];   // per t: A[64], K[64] (t < tconv)
__device__ __align__(16) float g_W[TMAX * 64];     // per-step suffix weights
__device__ __align__(16) float g_Phi[CMAX * 64];   // chunk transitions
__device__ __align__(16) float g_W2[CMAX * 64];    // chunk-level suffix weights
__device__ __align__(16) float g_Psi[SCMAX * 64];  // super-chunk transitions
__device__ __align__(16) float g_E [(size_t)CMAX  * BMAX * 8];
__device__ __align__(16) float g_E2[(size_t)SCMAX * BMAX * 8];
__device__ __align__(16) float g_X [(size_t)CMAX  * BMAX * 8];
__device__ __align__(16) float g_X2[(size_t)SCMAX * BMAX * 8];
__device__ __align__(16) float g_frozen[192];      // A[64], K[64], P[64]
__device__ int   g_tconv;

// ============================ riccati ======================================

__global__ void __launch_bounds__(64) riccati_kernel(
    const float* __restrict__ Fg, const float* __restrict__ Gg,
    const float* __restrict__ Hg, const float* __restrict__ Qg,
    const float* __restrict__ Rg, const float* __restrict__ P0g,
    float* __restrict__ Ps_out, int T)
{
    __shared__ float sF[72], sHF[72], sGQG[72], sC1[72], sC2[72];
    __shared__ float sP[72], sU[72], sV[72], sPn[72], sT2[72], sS[72];
    __shared__ float sK[72], sTmp[72];
    __shared__ float sRed[4];
    __shared__ int   sFlag;

    const int tid = threadIdx.x;
    const int i = tid >> 3, j = tid & 7;
    const int ij = i * 9 + j;

    sF[ij] = Fg[tid]; sTmp[ij] = Gg[tid]; sU[ij] = Qg[tid];
    sC2[ij] = Rg[tid]; sP[ij] = P0g[tid]; sV[ij] = Hg[tid];
    if (tid == 0) sFlag = 0;
    __syncthreads();

    {   // GQ -> sPn ; HF -> sHF
        float a = 0.f, b = 0.f;
        #pragma unroll
        for (int k = 0; k < 8; k++) {
            a += sTmp[i*9+k] * sU[k*9+j];
            b += sV[i*9+k]   * sF[k*9+j];
        }
        sPn[ij] = a; sHF[ij] = b;
    }
    __syncthreads();
    {   // GQG = GQ * G^T
        float a = 0.f;
        #pragma unroll
        for (int k = 0; k < 8; k++) a += sPn[i*9+k] * sTmp[j*9+k];
        sGQG[ij] = a;
    }
    __syncthreads();
    {   // C1 = H * GQG
        float a = 0.f;
        #pragma unroll
        for (int k = 0; k < 8; k++) a += sV[i*9+k] * sGQG[k*9+j];
        sC1[ij] = a;
    }
    __syncthreads();
    {   // C2 = C1 * H^T + R
        float a = sC2[ij];
        #pragma unroll
        for (int k = 0; k < 8; k++) a += sC1[i*9+k] * sV[j*9+k];
        __syncthreads();
        sC2[ij] = a;
    }
    __syncthreads();

    int conv = 0;
    bool frozen = false;
    for (int t = 0; t < T; t++) {
        {   // U = F*P ; V = HF*P
            float a = 0.f, b = 0.f;
            #pragma unroll
            for (int k = 0; k < 8; k++) {
                float p = sP[k*9+j];
                a = fmaf(sF[i*9+k],  p, a);
                b = fmaf(sHF[i*9+k], p, b);
            }
            sU[ij] = a; sV[ij] = b;
        }
        __syncthreads();
        {   // Pn = U*F^T + GQG ; T2 = V*F^T + C1 ; S = V*HF^T + C2
            float pn = sGQG[ij], t2 = sC1[ij], s = sC2[ij];
            #pragma unroll
            for (int k = 0; k < 8; k++) {
                float fk = sF[j*9+k];
                float vk = sV[i*9+k];
                pn = fmaf(sU[i*9+k], fk, pn);
                t2 = fmaf(vk, fk, t2);
                s  = fmaf(vk, sHF[j*9+k], s);
            }
            sPn[ij] = pn; sT2[ij] = t2; sS[ij] = s;
        }
        __syncthreads();
        // Gauss-Jordan on [S | T2]: solves S X = T2 (S SPD, no pivoting).
        if (tid < 16) {
            float a[8];
            #pragma unroll
            for (int r = 0; r < 8; r++)
                a[r] = (tid < 8) ? sS[r*9+tid] : sT2[r*9+(tid-8)];
            #pragma unroll
            for (int p = 0; p < 8; p++) {
                float c[8];
                #pragma unroll
                for (int r = 0; r < 8; r++)
                    c[r] = __shfl_sync(0x0000FFFFu, a[r], p, 16);
                float pr = 1.0f / c[p];
                a[p] *= pr;
                #pragma unroll
                for (int r = 0; r < 8; r++)
                    if (r != p) a[r] = fmaf(-c[r], a[p], a[r]);
            }
            if (tid >= 8) {
                const int row = tid - 8;
                #pragma unroll
                for (int r = 0; r < 8; r++) sK[row*9 + r] = a[r];
            }
        }
        __syncthreads();
        // P+ = Pn - K*T2 ; A = F - K*HF
        float krow[8];
        #pragma unroll
        for (int k = 0; k < 8; k++) krow[k] = sK[i*9+k];
        float pp = sPn[ij], aa = sF[ij];
        #pragma unroll
        for (int k = 0; k < 8; k++) {
            pp = fmaf(-krow[k], sT2[k*9+j], pp);
            aa = fmaf(-krow[k], sHF[k*9+j], aa);
        }
        sTmp[ij] = pp;
        __syncthreads();
        float pnew = 0.5f * (pp + sTmp[j*9+i]);
        float pold = sP[ij];
        sP[ij] = pnew;

        Ps_out[(size_t)t*64 + tid]          = pnew;
        g_AK[(size_t)t*128 + i*8 + j]       = aa;
        g_AK[(size_t)t*128 + 64 + i*8 + j]  = krow[j];

        float dm = fabsf(pnew - pold);
        float pm = fabsf(pnew);
        #pragma unroll
        for (int o = 16; o > 0; o >>= 1) {
            dm = fmaxf(dm, __shfl_xor_sync(0xFFFFFFFFu, dm, o));
            pm = fmaxf(pm, __shfl_xor_sync(0xFFFFFFFFu, pm, o));
        }
        if ((tid & 31) == 0) { sRed[(tid>>5)*2] = dm; sRed[(tid>>5)*2+1] = pm; }
        __syncthreads();
        if (tid == 0) {
            float d = fmaxf(sRed[0], sRed[2]);
            float p = fmaxf(sRed[1], sRed[3]);
            if (t >= 12 && d < 2e-4f * p) conv++; else conv = 0;
            sFlag = (conv >= 2) ? 1 : 0;
        }
        __syncthreads();
        if (sFlag) {
            g_frozen[tid]       = aa;
            g_frozen[64 + tid]  = krow[j];
            g_frozen[128 + tid] = pnew;
            if (tid == 0) g_tconv = t + 1;
            frozen = true;
            break;
        }
    }
    if (!frozen && tid == 0) g_tconv = T;
}

// ======================= shared A/K staging helper =========================

__device__ __forceinline__ void load_sAK(float* sAK, int L0, int Lc, int tconv,
                                         int tid, int nthr)
{
    const float4* gAK4 = (const float4*)g_AK;
    const float4* frz4 = (const float4*)g_frozen;
    for (int e = tid; e < Lc * 32; e += nthr) {
        const int t = L0 + (e >> 5);
        const int q = e & 31;
        ((float4*)sAK)[e] = (t < tconv) ? gAK4[(size_t)t * 32 + q] : frz4[q];
    }
}

// ============================ wprep ========================================

__global__ void __launch_bounds__(64) wprep_kernel(float* __restrict__ Ps_out, int T)
{
    const int c  = blockIdx.x;
    const int L0 = c * LCH;
    const int Lc = min(LCH, T - L0);
    const int tconv = g_tconv;

    __shared__ __align__(16) float sAK[LCH * 128];
    __shared__ float sM[2][72];

    const int tid = threadIdx.x;
    const int i = tid >> 3, j = tid & 7;
    load_sAK(sAK, L0, Lc, tconv, tid, 64);
    sM[0][i*9+j] = (i == j) ? 1.f : 0.f;

    for (int t = max(L0, tconv); t < L0 + Lc; t++)
        Ps_out[(size_t)t*64 + tid] = g_frozen[128 + tid];
    __syncthreads();

    int pb = 0;
    for (int jj = Lc - 1; jj >= 0; jj--) {
        const float* a = sAK + jj * 128;
        float w = 0.f, m = 0.f;
        #pragma unroll
        for (int k = 0; k < 8; k++) {
            float mk = sM[pb][i*9+k];
            w = fmaf(mk, a[64 + k*8 + j], w);
            m = fmaf(mk, a[k*8 + j],      m);
        }
        g_W[(size_t)(L0 + jj)*64 + tid] = w;
        sM[pb ^ 1][i*9+j] = m;
        pb ^= 1;
        __syncthreads();
    }
    g_Phi[c*64 + tid] = sM[pb][i*9+j];
}

// ============================ wprep2 =======================================

__global__ void __launch_bounds__(64) wprep2_kernel(int C)
{
    const int s  = blockIdx.x;
    const int c0 = s * SL;
    const int nc = min(SL, C - c0);
    __shared__ float sM[2][72];
    __shared__ float sPhi[SL * 64];

    const int tid = threadIdx.x;
    const int i = tid >> 3, j = tid & 7;
    for (int e = tid; e < nc * 64; e += 64) sPhi[e] = g_Phi[c0 * 64 + e];
    sM[0][i*9+j] = (i == j) ? 1.f : 0.f;
    __syncthreads();

    int pb = 0;
    for (int jj = nc - 1; jj >= 0; jj--) {
        g_W2[(c0 + jj)*64 + tid] = sM[pb][i*9+j];
        const float* ph = sPhi + jj * 64;
        float m = 0.f;
        #pragma unroll
        for (int k = 0; k < 8; k++)
            m = fmaf(sM[pb][i*9+k], ph[k*8 + j], m);
        sM[pb ^ 1][i*9+j] = m;
        pb ^= 1;
        __syncthreads();
    }
    g_Psi[s*64 + tid] = sM[pb][i*9+j];
}

// ============================ ends =========================================
// Direct global Y reads, 2 batches/thread, tiny smem. Fast path (Lc==LCH)
// is branch-free so all 40 LDG.128 are hoistable -> MLP-limited, not latency.

__device__ __forceinline__ void ends_acc_step(
    float* __restrict__ accA, float* __restrict__ accB,
    const float4 a0, const float4 a1, const float4 b0, const float4 b1,
    const float* __restrict__ w)
{
    #pragma unroll
    for (int i = 0; i < 8; i++) {
        const float w0 = w[i*8+0], w1 = w[i*8+1], w2 = w[i*8+2], w3 = w[i*8+3];
        const float w4 = w[i*8+4], w5 = w[i*8+5], w6 = w[i*8+6], w7 = w[i*8+7];
        float sa = accA[i], sb = accB[i];
        sa = fmaf(w0, a0.x, sa);  sb = fmaf(w0, b0.x, sb);
        sa = fmaf(w1, a0.y, sa);  sb = fmaf(w1, b0.y, sb);
        sa = fmaf(w2, a0.z, sa);  sb = fmaf(w2, b0.z, sb);
        sa = fmaf(w3, a0.w, sa);  sb = fmaf(w3, b0.w, sb);
        sa = fmaf(w4, a1.x, sa);  sb = fmaf(w4, b1.x, sb);
        sa = fmaf(w5, a1.y, sa);  sb = fmaf(w5, b1.y, sb);
        sa = fmaf(w6, a1.z, sa);  sb = fmaf(w6, b1.z, sb);
        sa = fmaf(w7, a1.w, sa);  sb = fmaf(w7, b1.w, sb);
        accA[i] = sa; accB[i] = sb;
    }
}

__global__ void __launch_bounds__(128, 1) ends_kernel(
    const float* __restrict__ Y, int B, int T)
{
    const int c  = blockIdx.x;
    const int L0 = c * LCH;
    const int Lc = min(LCH, T - L0);

    __shared__ __align__(16) float sW[LCH * 64];
    const int tid = threadIdx.x;
    for (int e = tid; e < Lc * 16; e += 128)
        ((float4*)sW)[e] = ((const float4*)(g_W + (size_t)L0 * 64))[e];
    __syncthreads();

    const int bA = blockIdx.y * 256 + tid;
    const int bB = bA + 128;
    const int bsA = (bA < B) ? bA : 0;
    const int bsB = (bB < B) ? bB : 0;
    const float4* yA = (const float4*)(Y + ((size_t)bsA * T + L0) * 8);
    const float4* yB = (const float4*)(Y + ((size_t)bsB * T + L0) * 8);

    float accA[8], accB[8];
    #pragma unroll
    for (int i = 0; i < 8; i++) { accA[i] = 0.f; accB[i] = 0.f; }

    if (Lc == LCH) {
        // branch-free: all loads hoistable
        #pragma unroll
        for (int jj = 0; jj < LCH; jj++) {
            const float4 a0 = yA[2*jj], a1 = yA[2*jj + 1];
            const float4 b0 = yB[2*jj], b1 = yB[2*jj + 1];
            ends_acc_step(accA, accB, a0, a1, b0, b1, sW + jj * 64);
        }
    } else {
        for (int jj = 0; jj < Lc; jj++) {
            const float4 a0 = yA[2*jj], a1 = yA[2*jj + 1];
            const float4 b0 = yB[2*jj], b1 = yB[2*jj + 1];
            ends_acc_step(accA, accB, a0, a1, b0, b1, sW + jj * 64);
        }
    }
    if (bA < B) {
        float4* eo = (float4*)(g_E + ((size_t)c * B + bA) * 8);
        eo[0] = make_float4(accA[0], accA[1], accA[2], accA[3]);
        eo[1] = make_float4(accA[4], accA[5], accA[6], accA[7]);
    }
    if (bB < B) {
        float4* eo = (float4*)(g_E + ((size_t)c * B + bB) * 8);
        eo[0] = make_float4(accB[0], accB[1], accB[2], accB[3]);
        eo[1] = make_float4(accB[4], accB[5], accB[6], accB[7]);
    }
}

// ============================ combineA =====================================

__global__ void __launch_bounds__(128, 1) combineA_kernel(int B, int C)
{
    const int s  = blockIdx.x;
    const int c0 = s * SL;
    const int nc = min(SL, C - c0);

    __shared__ __align__(16) float sW2[SL * 64];
    const int tid = threadIdx.x;
    for (int e = tid; e < nc * 16; e += 128)
        ((float4*)sW2)[e] = ((const float4*)(g_W2 + c0 * 64))[e];
    __syncthreads();

    const int b = blockIdx.y * 128 + tid;
    const bool ok = (b < B);
    const int bs = ok ? b : 0;

    float acc[8];
    #pragma unroll
    for (int i = 0; i < 8; i++) acc[i] = 0.f;

    if (nc == SL) {
        #pragma unroll
        for (int jj = 0; jj < SL; jj++) {
            const float4* ep = (const float4*)(g_E + ((size_t)(c0 + jj) * B + bs) * 8);
            const float4 e0 = ep[0], e1 = ep[1];
            const float* w = sW2 + jj * 64;
            #pragma unroll
            for (int i = 0; i < 8; i++) {
                float a = acc[i];
                a = fmaf(w[i*8+0], e0.x, a); a = fmaf(w[i*8+1], e0.y, a);
                a = fmaf(w[i*8+2], e0.z, a); a = fmaf(w[i*8+3], e0.w, a);
                a = fmaf(w[i*8+4], e1.x, a); a = fmaf(w[i*8+5], e1.y, a);
                a = fmaf(w[i*8+6], e1.z, a); a = fmaf(w[i*8+7], e1.w, a);
                acc[i] = a;
            }
        }
    } else {
        for (int jj = 0; jj < nc; jj++) {
            const float4* ep = (const float4*)(g_E + ((size_t)(c0 + jj) * B + bs) * 8);
            const float4 e0 = ep[0], e1 = ep[1];
            const float* w = sW2 + jj * 64;
            #pragma unroll
            for (int i = 0; i < 8; i++) {
                float a = acc[i];
                a = fmaf(w[i*8+0], e0.x, a); a = fmaf(w[i*8+1], e0.y, a);
                a = fmaf(w[i*8+2], e0.z, a); a = fmaf(w[i*8+3], e0.w, a);
                a = fmaf(w[i*8+4], e1.x, a); a = fmaf(w[i*8+5], e1.y, a);
                a = fmaf(w[i*8+6], e1.z, a); a = fmaf(w[i*8+7], e1.w, a);
                acc[i] = a;
            }
        }
    }
    if (ok) {
        float4* eo = (float4*)(g_E2 + ((size_t)s * B + b) * 8);
        eo[0] = make_float4(acc[0], acc[1], acc[2], acc[3]);
        eo[1] = make_float4(acc[4], acc[5], acc[6], acc[7]);
    }
}

// ============================ combineB =====================================

__global__ void __launch_bounds__(256) combineB_kernel(
    const float* __restrict__ x0, int B, int SC)
{
    __shared__ float sPsi[SCMAX * 64];
    const int tid = threadIdx.x;
    for (int e = tid; e < SC * 64; e += 256) sPsi[e] = g_Psi[e];
    __syncthreads();

    const int b = blockIdx.x * 256 + tid;
    const bool ok = (b < B);
    const int bs = ok ? b : 0;

    float x[8];
    {
        const float4* xp = (const float4*)(x0 + bs * 8);
        float4 a = xp[0], b4 = xp[1];
        x[0]=a.x; x[1]=a.y; x[2]=a.z; x[3]=a.w;
        x[4]=b4.x; x[5]=b4.y; x[6]=b4.z; x[7]=b4.w;
    }

    for (int s = 0; s < SC; s++) {
        if (ok) {
            float4* xo = (float4*)(g_X2 + ((size_t)s * B + b) * 8);
            xo[0] = make_float4(x[0], x[1], x[2], x[3]);
            xo[1] = make_float4(x[4], x[5], x[6], x[7]);
        }
        const float4* ep = (const float4*)(g_E2 + ((size_t)s * B + bs) * 8);
        const float4 e0 = ep[0], e1 = ep[1];
        const float* pr = sPsi + s * 64;
        float xn[8];
        #pragma unroll
        for (int i = 0; i < 8; i++) {
            float a = 0.f;
            #pragma unroll
            for (int k = 0; k < 8; k++) a = fmaf(pr[i*8+k], x[k], a);
            xn[i] = a;
        }
        xn[0]+=e0.x; xn[1]+=e0.y; xn[2]+=e0.z; xn[3]+=e0.w;
        xn[4]+=e1.x; xn[5]+=e1.y; xn[6]+=e1.z; xn[7]+=e1.w;
        #pragma unroll
        for (int i = 0; i < 8; i++) x[i] = xn[i];
    }
}

// ============================ combineC =====================================

__global__ void __launch_bounds__(128, 1) combineC_kernel(int B, int C)
{
    const int s  = blockIdx.x;
    const int c0 = s * SL;
    const int nc = min(SL, C - c0);

    __shared__ __align__(16) float sPhi[SL * 64];
    const int tid = threadIdx.x;
    for (int e = tid; e < nc * 16; e += 128)
        ((float4*)sPhi)[e] = ((const float4*)(g_Phi + c0 * 64))[e];
    __syncthreads();

    const int b = blockIdx.y * 128 + tid;
    const bool ok = (b < B);
    const int bs = ok ? b : 0;

    float x[8];
    {
        const float4* xp = (const float4*)(g_X2 + ((size_t)s * B + bs) * 8);
        float4 a = xp[0], b4 = xp[1];
        x[0]=a.x; x[1]=a.y; x[2]=a.z; x[3]=a.w;
        x[4]=b4.x; x[5]=b4.y; x[6]=b4.z; x[7]=b4.w;
    }

    for (int jj = 0; jj < nc; jj++) {
        const int c = c0 + jj;
        if (ok) {
            float4* xo = (float4*)(g_X + ((size_t)c * B + b) * 8);
            xo[0] = make_float4(x[0], x[1], x[2], x[3]);
            xo[1] = make_float4(x[4], x[5], x[6], x[7]);
        }
        if (jj < nc - 1) {
            const float4* ep = (const float4*)(g_E + ((size_t)c * B + bs) * 8);
            const float4 e0 = ep[0], e1 = ep[1];
            const float* pr = sPhi + jj * 64;
            float xn[8];
            #pragma unroll
            for (int i = 0; i < 8; i++) {
                float a = 0.f;
                #pragma unroll
                for (int k = 0; k < 8; k++) a = fmaf(pr[i*8+k], x[k], a);
                xn[i] = a;
            }
            xn[0]+=e0.x; xn[1]+=e0.y; xn[2]+=e0.z; xn[3]+=e0.w;
            xn[4]+=e1.x; xn[5]+=e1.y; xn[6]+=e1.z; xn[7]+=e1.w;
            #pragma unroll
            for (int i = 0; i < 8; i++) x[i] = xn[i];
        }
    }
}

// ============================ scan =========================================
// 2 chains/thread; fast path prefetches ALL y into registers before the
// serial chain, so LDG latency fully overlaps the dependent FMA chain.

__global__ void __launch_bounds__(NT, 1) scan_kernel(
    const float* __restrict__ Y, float* __restrict__ traj, int B, int T)
{
    const int c  = blockIdx.x;
    const int L0 = c * LCH;
    const int Lc = min(LCH, T - L0);
    const int tconv = g_tconv;

    __shared__ __align__(16) float sAK[LCH * 128];
    __shared__ __align__(16) float sOut[NB * SROW];

    const int tid = threadIdx.x;
    load_sAK(sAK, L0, Lc, tconv, tid, NT);

    const int bA = blockIdx.y * NB + tid;
    const int bsA = (bA < B) ? bA : 0;
    const int bB = bA + NT;
    const int bsB = (bB < B) ? bB : 0;
    const float4* yA = (const float4*)(Y + ((size_t)bsA * T + L0) * 8);
    const float4* yB = (const float4*)(Y + ((size_t)bsB * T + L0) * 8);
    float* oA = sOut + tid * SROW;
    float* oB = sOut + (tid + NT) * SROW;

    float xA[8], xB[8];
    {
        const float4* xp = (const float4*)(g_X + ((size_t)c * B + bsA) * 8);
        float4 a = xp[0], b4 = xp[1];
        xA[0]=a.x; xA[1]=a.y; xA[2]=a.z; xA[3]=a.w;
        xA[4]=b4.x; xA[5]=b4.y; xA[6]=b4.z; xA[7]=b4.w;
    }
    {
        const float4* xp = (const float4*)(g_X + ((size_t)c * B + bsB) * 8);
        float4 a = xp[0], b4 = xp[1];
        xB[0]=a.x; xB[1]=a.y; xB[2]=a.z; xB[3]=a.w;
        xB[4]=b4.x; xB[5]=b4.y; xB[6]=b4.z; xB[7]=b4.w;
    }

    if (Lc == LCH) {
        // prefetch the entire y window for both chains (branch-free)
        float4 vA[2 * LCH], vB[2 * LCH];
        #pragma unroll
        for (int q = 0; q < 2 * LCH; q++) { vA[q] = yA[q]; vB[q] = yB[q]; }
        __syncthreads();   // sAK ready

        #pragma unroll
        for (int jj = 0; jj < LCH; jj++) {
            const float4 ya0 = vA[2*jj], ya1 = vA[2*jj + 1];
            const float4 yb0 = vB[2*jj], yb1 = vB[2*jj + 1];
            const float* a = sAK + jj * 128;
            float xnA[8], xnB[8];
            #pragma unroll
            for (int i = 0; i < 8; i++) {
                const float* ar = a + i * 8;
                const float* kr = a + 64 + i * 8;
                float sA0 = ar[0] * xA[0];
                float sA1 = kr[0] * ya0.x;
                float sB0 = ar[0] * xB[0];
                float sB1 = kr[0] * yb0.x;
                sA0 = fmaf(ar[1], xA[1], sA0);  sB0 = fmaf(ar[1], xB[1], sB0);
                sA1 = fmaf(kr[1], ya0.y, sA1);  sB1 = fmaf(kr[1], yb0.y, sB1);
                sA0 = fmaf(ar[2], xA[2], sA0);  sB0 = fmaf(ar[2], xB[2], sB0);
                sA1 = fmaf(kr[2], ya0.z, sA1);  sB1 = fmaf(kr[2], yb0.z, sB1);
                sA0 = fmaf(ar[3], xA[3], sA0);  sB0 = fmaf(ar[3], xB[3], sB0);
                sA1 = fmaf(kr[3], ya0.w, sA1);  sB1 = fmaf(kr[3], yb0.w, sB1);
                sA0 = fmaf(ar[4], xA[4], sA0);  sB0 = fmaf(ar[4], xB[4], sB0);
                sA1 = fmaf(kr[4], ya1.x, sA1);  sB1 = fmaf(kr[4], yb1.x, sB1);
                sA0 = fmaf(ar[5], xA[5], sA0);  sB0 = fmaf(ar[5], xB[5], sB0);
                sA1 = fmaf(kr[5], ya1.y, sA1);  sB1 = fmaf(kr[5], yb1.y, sB1);
                sA0 = fmaf(ar[6], xA[6], sA0);  sB0 = fmaf(ar[6], xB[6], sB0);
                sA1 = fmaf(kr[6], ya1.z, sA1);  sB1 = fmaf(kr[6], yb1.z, sB1);
                sA0 = fmaf(ar[7], xA[7], sA0);  sB0 = fmaf(ar[7], xB[7], sB0);
                sA1 = fmaf(kr[7], ya1.w, sA1);  sB1 = fmaf(kr[7], yb1.w, sB1);
                xnA[i] = sA0 + sA1;
                xnB[i] = sB0 + sB1;
            }
            #pragma unroll
            for (int i = 0; i < 8; i++) { xA[i] = xnA[i]; xB[i] = xnB[i]; }
            ((float4*)oA)[2*jj]     = make_float4(xA[0], xA[1], xA[2], xA[3]);
            ((float4*)oA)[2*jj + 1] = make_float4(xA[4], xA[5], xA[6], xA[7]);
            ((float4*)oB)[2*jj]     = make_float4(xB[0], xB[1], xB[2], xB[3]);
            ((float4*)oB)[2*jj + 1] = make_float4(xB[4], xB[5], xB[6], xB[7]);
        }
    } else {
        __syncthreads();   // sAK ready
        for (int jj = 0; jj < Lc; jj++) {
            const float4 ya0 = yA[2*jj], ya1 = yA[2*jj + 1];
            const float4 yb0 = yB[2*jj], yb1 = yB[2*jj + 1];
            const float* a = sAK + jj * 128;
            float xnA[8], xnB[8];
            #pragma unroll
            for (int i = 0; i < 8; i++) {
                const float* ar = a + i * 8;
                const float* kr = a + 64 + i * 8;
                float sA0 = ar[0] * xA[0];
                float sA1 = kr[0] * ya0.x;
                float sB0 = ar[0] * xB[0];
                float sB1 = kr[0] * yb0.x;
                sA0 = fmaf(ar[1], xA[1], sA0);  sB0 = fmaf(ar[1], xB[1], sB0);
                sA1 = fmaf(kr[1], ya0.y, sA1);  sB1 = fmaf(kr[1], yb0.y, sB1);
                sA0 = fmaf(ar[2], xA[2], sA0);  sB0 = fmaf(ar[2], xB[2], sB0);
                sA1 = fmaf(kr[2], ya0.z, sA1);  sB1 = fmaf(kr[2], yb0.z, sB1);
                sA0 = fmaf(ar[3], xA[3], sA0);  sB0 = fmaf(ar[3], xB[3], sB0);
                sA1 = fmaf(kr[3], ya0.w, sA1);  sB1 = fmaf(kr[3], yb0.w, sB1);
                sA0 = fmaf(ar[4], xA[4], sA0);  sB0 = fmaf(ar[4], xB[4], sB0);
                sA1 = fmaf(kr[4], ya1.x, sA1);  sB1 = fmaf(kr[4], yb1.x, sB1);
                sA0 = fmaf(ar[5], xA[5], sA0);  sB0 = fmaf(ar[5], xB[5], sB0);
                sA1 = fmaf(kr[5], ya1.y, sA1);  sB1 = fmaf(kr[5], yb1.y, sB1);
                sA0 = fmaf(ar[6], xA[6], sA0);  sB0 = fmaf(ar[6], xB[6], sB0);
                sA1 = fmaf(kr[6], ya1.z, sA1);  sB1 = fmaf(kr[6], yb1.z, sB1);
                sA0 = fmaf(ar[7], xA[7], sA0);  sB0 = fmaf(ar[7], xB[7], sB0);
                sA1 = fmaf(kr[7], ya1.w, sA1);  sB1 = fmaf(kr[7], yb1.w, sB1);
                xnA[i] = sA0 + sA1;
                xnB[i] = sB0 + sB1;
            }
            #pragma unroll
            for (int i = 0; i < 8; i++) { xA[i] = xnA[i]; xB[i] = xnB[i]; }
            ((float4*)oA)[2*jj]     = make_float4(xA[0], xA[1], xA[2], xA[3]);
            ((float4*)oA)[2*jj + 1] = make_float4(xA[4], xA[5], xA[6], xA[7]);
            ((float4*)oB)[2*jj]     = make_float4(xB[0], xB[1], xB[2], xB[3]);
            ((float4*)oB)[2*jj + 1] = make_float4(xB[4], xB[5], xB[6], xB[7]);
        }
    }
    __syncthreads();

    // coalesced store of the output tile
    {
        float4* T4 = (float4*)traj;
        const int b0 = blockIdx.y * NB;
        for (int idx = tid; idx < NB * 2 * LCH; idx += NT) {
            const int row = idx / (2 * LCH);
            const int col = idx - row * (2 * LCH);
            const int b = b0 + row;
            if (b < B && col < 2 * Lc)
                T4[((size_t)b * T + L0) * 2 + col] =
                    ((const float4*)(sOut + row * SROW))[col];
        }
    }
}

// ============================ launch =======================================

extern "C" void kernel_launch(void* const* d_in, const int* in_sizes, int n_in,
                              void* d_out, int out_size)
{
    const float* Y  = (const float*)d_in[0];
    const float* F  = (const float*)d_in[1];
    const float* G  = (const float*)d_in[2];
    const float* H  = (const float*)d_in[3];
    const float* Q  = (const float*)d_in[4];
    const float* R  = (const float*)d_in[5];
    const float* x0 = (const float*)d_in[6];
    const float* P0 = (const float*)d_in[7];

    const int B  = in_sizes[6] / 8;
    const int T  = in_sizes[0] / (B * 8);
    const int C  = (T + LCH - 1) / LCH;
    const int SC = (C + SL - 1) / SL;

    float* traj = (float*)d_out;                 // (B, T, 8)
    float* Ps   = traj + (size_t)B * T * 8;      // (T, 8, 8)

    riccati_kernel<<<1, 64>>>(F, G, H, Q, R, P0, Ps, T);
    wprep_kernel<<<C, 64>>>(Ps, T);
    wprep2_kernel<<<SC, 64>>>(C);
    {
        dim3 grid(C, (B + 255) / 256);
        ends_kernel<<<grid, 128>>>(Y, B, T);
    }
    {
        dim3 grid(SC, (B + 127) / 128);
        combineA_kernel<<<grid, 128>>>(B, C);
    }
    combineB_kernel<<<(B + 255) / 256, 256>>>(x0, B, SC);
    {
        dim3 grid(SC, (B + 127) / 128);
        combineC_kernel<<<grid, 128>>>(B, C);
    }
    {
        dim3 grid(C, (B + NB - 1) / NB);
        scan_kernel<<<grid, NT>>>(Y, traj, B, T);
    }
}

// round 13
// speedup vs baseline: 1.5570x; 1.0130x over previous
#include <cuda_runtime.h>

// ---------------------------------------------------------------------------
// KF: batched square-root Kalman filter. B=2048, T=1000, n=d=8.
// Two-level chunked linear-scan: LCH=10 steps/chunk, SL=10 chunks/super.
// Pipeline: riccati -> wprep -> ends -> combineA(+W2 preamble) -> combineB
//           -> combineC -> scan.
// ---------------------------------------------------------------------------

#define LCH  10
#define SL   10
#define TMAX 1024
#define CMAX ((TMAX + LCH - 1) / LCH)
#define SCMAX ((CMAX + SL - 1) / SL)
#define BMAX 2048
#define NB   128            // batches per block tile in scan
#define NT   64             // threads per block in scan (2 batches each)
#define SROW (LCH * 8 + 4)  // 84 floats = 21 float4 (odd) -> conflict-free LDS

__device__ __align__(16) float g_AK[TMAX * 128];   // per t: A[64], K[64] (t < tconv)
__device__ __align__(16) float g_W[TMAX * 64];     // per-step suffix weights
__device__ __align__(16) float g_Phi[CMAX * 64];   // chunk transitions
__device__ __align__(16) float g_Psi[SCMAX * 64];  // super-chunk transitions
__device__ __align__(16) float g_E [(size_t)CMAX  * BMAX * 8];
__device__ __align__(16) float g_E2[(size_t)SCMAX * BMAX * 8];
__device__ __align__(16) float g_X [(size_t)CMAX  * BMAX * 8];
__device__ __align__(16) float g_X2[(size_t)SCMAX * BMAX * 8];
__device__ __align__(16) float g_frozen[192];      // A[64], K[64], P[64]
__device__ int   g_tconv;

// ============================ riccati ======================================

__global__ void __launch_bounds__(64) riccati_kernel(
    const float* __restrict__ Fg, const float* __restrict__ Gg,
    const float* __restrict__ Hg, const float* __restrict__ Qg,
    const float* __restrict__ Rg, const float* __restrict__ P0g,
    float* __restrict__ Ps_out, int T)
{
    __shared__ float sF[72], sHF[72], sGQG[72], sC1[72], sC2[72];
    __shared__ float sP[72], sU[72], sV[72], sPn[72], sT2[72], sS[72];
    __shared__ float sK[72], sTmp[72];
    __shared__ float sRed[4];
    __shared__ int   sFlag;

    const int tid = threadIdx.x;
    const int i = tid >> 3, j = tid & 7;
    const int ij = i * 9 + j;

    sF[ij] = Fg[tid]; sTmp[ij] = Gg[tid]; sU[ij] = Qg[tid];
    sC2[ij] = Rg[tid]; sP[ij] = P0g[tid]; sV[ij] = Hg[tid];
    if (tid == 0) sFlag = 0;
    __syncthreads();

    {   // GQ -> sPn ; HF -> sHF
        float a = 0.f, b = 0.f;
        #pragma unroll
        for (int k = 0; k < 8; k++) {
            a += sTmp[i*9+k] * sU[k*9+j];
            b += sV[i*9+k]   * sF[k*9+j];
        }
        sPn[ij] = a; sHF[ij] = b;
    }
    __syncthreads();
    {   // GQG = GQ * G^T
        float a = 0.f;
        #pragma unroll
        for (int k = 0; k < 8; k++) a += sPn[i*9+k] * sTmp[j*9+k];
        sGQG[ij] = a;
    }
    __syncthreads();
    {   // C1 = H * GQG
        float a = 0.f;
        #pragma unroll
        for (int k = 0; k < 8; k++) a += sV[i*9+k] * sGQG[k*9+j];
        sC1[ij] = a;
    }
    __syncthreads();
    {   // C2 = C1 * H^T + R
        float a = sC2[ij];
        #pragma unroll
        for (int k = 0; k < 8; k++) a += sC1[i*9+k] * sV[j*9+k];
        __syncthreads();
        sC2[ij] = a;
    }
    __syncthreads();

    int conv = 0;
    bool frozen = false;
    for (int t = 0; t < T; t++) {
        {   // U = F*P ; V = HF*P
            float a = 0.f, b = 0.f;
            #pragma unroll
            for (int k = 0; k < 8; k++) {
                float p = sP[k*9+j];
                a = fmaf(sF[i*9+k],  p, a);
                b = fmaf(sHF[i*9+k], p, b);
            }
            sU[ij] = a; sV[ij] = b;
        }
        __syncthreads();
        {   // Pn = U*F^T + GQG ; T2 = V*F^T + C1 ; S = V*HF^T + C2
            float pn = sGQG[ij], t2 = sC1[ij], s = sC2[ij];
            #pragma unroll
            for (int k = 0; k < 8; k++) {
                float fk = sF[j*9+k];
                float vk = sV[i*9+k];
                pn = fmaf(sU[i*9+k], fk, pn);
                t2 = fmaf(vk, fk, t2);
                s  = fmaf(vk, sHF[j*9+k], s);
            }
            sPn[ij] = pn; sT2[ij] = t2; sS[ij] = s;
        }
        __syncthreads();
        // Gauss-Jordan on [S | T2]: solves S X = T2 (S SPD, no pivoting).
        if (tid < 16) {
            float a[8];
            #pragma unroll
            for (int r = 0; r < 8; r++)
                a[r] = (tid < 8) ? sS[r*9+tid] : sT2[r*9+(tid-8)];
            #pragma unroll
            for (int p = 0; p < 8; p++) {
                float c[8];
                #pragma unroll
                for (int r = 0; r < 8; r++)
                    c[r] = __shfl_sync(0x0000FFFFu, a[r], p, 16);
                float pr = 1.0f / c[p];
                a[p] *= pr;
                #pragma unroll
                for (int r = 0; r < 8; r++)
                    if (r != p) a[r] = fmaf(-c[r], a[p], a[r]);
            }
            if (tid >= 8) {
                const int row = tid - 8;
                #pragma unroll
                for (int r = 0; r < 8; r++) sK[row*9 + r] = a[r];
            }
        }
        __syncthreads();
        // P+ = Pn - K*T2 ; A = F - K*HF
        float krow[8];
        #pragma unroll
        for (int k = 0; k < 8; k++) krow[k] = sK[i*9+k];
        float pp = sPn[ij], aa = sF[ij];
        #pragma unroll
        for (int k = 0; k < 8; k++) {
            pp = fmaf(-krow[k], sT2[k*9+j], pp);
            aa = fmaf(-krow[k], sHF[k*9+j], aa);
        }
        sTmp[ij] = pp;
        __syncthreads();
        float pnew = 0.5f * (pp + sTmp[j*9+i]);
        float pold = sP[ij];
        sP[ij] = pnew;

        Ps_out[(size_t)t*64 + tid]          = pnew;
        g_AK[(size_t)t*128 + i*8 + j]       = aa;
        g_AK[(size_t)t*128 + 64 + i*8 + j]  = krow[j];

        float dm = fabsf(pnew - pold);
        float pm = fabsf(pnew);
        #pragma unroll
        for (int o = 16; o > 0; o >>= 1) {
            dm = fmaxf(dm, __shfl_xor_sync(0xFFFFFFFFu, dm, o));
            pm = fmaxf(pm, __shfl_xor_sync(0xFFFFFFFFu, pm, o));
        }
        if ((tid & 31) == 0) { sRed[(tid>>5)*2] = dm; sRed[(tid>>5)*2+1] = pm; }
        __syncthreads();
        if (tid == 0) {
            float d = fmaxf(sRed[0], sRed[2]);
            float p = fmaxf(sRed[1], sRed[3]);
            if (t >= 12 && d < 2e-4f * p) conv++; else conv = 0;
            sFlag = (conv >= 2) ? 1 : 0;
        }
        __syncthreads();
        if (sFlag) {
            g_frozen[tid]       = aa;
            g_frozen[64 + tid]  = krow[j];
            g_frozen[128 + tid] = pnew;
            if (tid == 0) g_tconv = t + 1;
            frozen = true;
            break;
        }
    }
    if (!frozen && tid == 0) g_tconv = T;
}

// ======================= shared A/K staging helper =========================

__device__ __forceinline__ void load_sAK(float* sAK, int L0, int Lc, int tconv,
                                         int tid, int nthr)
{
    const float4* gAK4 = (const float4*)g_AK;
    const float4* frz4 = (const float4*)g_frozen;
    for (int e = tid; e < Lc * 32; e += nthr) {
        const int t = L0 + (e >> 5);
        const int q = e & 31;
        ((float4*)sAK)[e] = (t < tconv) ? gAK4[(size_t)t * 32 + q] : frz4[q];
    }
}

// ============================ wprep ========================================

__global__ void __launch_bounds__(64) wprep_kernel(float* __restrict__ Ps_out, int T)
{
    const int c  = blockIdx.x;
    const int L0 = c * LCH;
    const int Lc = min(LCH, T - L0);
    const int tconv = g_tconv;

    __shared__ __align__(16) float sAK[LCH * 128];
    __shared__ float sM[2][72];

    const int tid = threadIdx.x;
    const int i = tid >> 3, j = tid & 7;
    load_sAK(sAK, L0, Lc, tconv, tid, 64);
    sM[0][i*9+j] = (i == j) ? 1.f : 0.f;

    for (int t = max(L0, tconv); t < L0 + Lc; t++)
        Ps_out[(size_t)t*64 + tid] = g_frozen[128 + tid];
    __syncthreads();

    int pb = 0;
    for (int jj = Lc - 1; jj >= 0; jj--) {
        const float* a = sAK + jj * 128;
        float w = 0.f, m = 0.f;
        #pragma unroll
        for (int k = 0; k < 8; k++) {
            float mk = sM[pb][i*9+k];
            w = fmaf(mk, a[64 + k*8 + j], w);
            m = fmaf(mk, a[k*8 + j],      m);
        }
        g_W[(size_t)(L0 + jj)*64 + tid] = w;
        sM[pb ^ 1][i*9+j] = m;
        pb ^= 1;
        __syncthreads();
    }
    g_Phi[c*64 + tid] = sM[pb][i*9+j];
}

// ============================ ends =========================================
// Direct global Y reads, 2 batches/thread, tiny smem. (R10 configuration —
// measured fastest: 29.3us, occ 32.5%.)

__global__ void __launch_bounds__(128) ends_kernel(
    const float* __restrict__ Y, int B, int T)
{
    const int c  = blockIdx.x;
    const int L0 = c * LCH;
    const int Lc = min(LCH, T - L0);

    __shared__ __align__(16) float sW[LCH * 64];
    const int tid = threadIdx.x;
    for (int e = tid; e < Lc * 16; e += 128)
        ((float4*)sW)[e] = ((const float4*)(g_W + (size_t)L0 * 64))[e];
    __syncthreads();

    const int bA = blockIdx.y * 256 + tid;
    const int bB = bA + 128;
    const int bsA = (bA < B) ? bA : 0;
    const int bsB = (bB < B) ? bB : 0;
    const float4* yA = (const float4*)(Y + ((size_t)bsA * T + L0) * 8);
    const float4* yB = (const float4*)(Y + ((size_t)bsB * T + L0) * 8);

    float accA[8], accB[8];
    #pragma unroll
    for (int i = 0; i < 8; i++) { accA[i] = 0.f; accB[i] = 0.f; }

    #pragma unroll
    for (int jj = 0; jj < LCH; jj++) {
        if (jj < Lc) {
            const float4 a0 = yA[2*jj], a1 = yA[2*jj + 1];
            const float4 b0 = yB[2*jj], b1 = yB[2*jj + 1];
            const float* w = sW + jj * 64;
            #pragma unroll
            for (int i = 0; i < 8; i++) {
                const float w0 = w[i*8+0], w1 = w[i*8+1], w2 = w[i*8+2], w3 = w[i*8+3];
                const float w4 = w[i*8+4], w5 = w[i*8+5], w6 = w[i*8+6], w7 = w[i*8+7];
                float sa = accA[i], sb = accB[i];
                sa = fmaf(w0, a0.x, sa);  sb = fmaf(w0, b0.x, sb);
                sa = fmaf(w1, a0.y, sa);  sb = fmaf(w1, b0.y, sb);
                sa = fmaf(w2, a0.z, sa);  sb = fmaf(w2, b0.z, sb);
                sa = fmaf(w3, a0.w, sa);  sb = fmaf(w3, b0.w, sb);
                sa = fmaf(w4, a1.x, sa);  sb = fmaf(w4, b1.x, sb);
                sa = fmaf(w5, a1.y, sa);  sb = fmaf(w5, b1.y, sb);
                sa = fmaf(w6, a1.z, sa);  sb = fmaf(w6, b1.z, sb);
                sa = fmaf(w7, a1.w, sa);  sb = fmaf(w7, b1.w, sb);
                accA[i] = sa; accB[i] = sb;
            }
        }
    }
    if (bA < B) {
        float4* eo = (float4*)(g_E + ((size_t)c * B + bA) * 8);
        eo[0] = make_float4(accA[0], accA[1], accA[2], accA[3]);
        eo[1] = make_float4(accA[4], accA[5], accA[6], accA[7]);
    }
    if (bB < B) {
        float4* eo = (float4*)(g_E + ((size_t)c * B + bB) * 8);
        eo[0] = make_float4(accB[0], accB[1], accB[2], accB[3]);
        eo[1] = make_float4(accB[4], accB[5], accB[6], accB[7]);
    }
}

// ============================ combineA =====================================
// Preamble (64 threads): W2 suffix weights + Psi from g_Phi (folds wprep2).
// Body: E2_{s,b} = sum_j W2_j e_{c0+j,b}.

__global__ void __launch_bounds__(128) combineA_kernel(int B, int C)
{
    const int s  = blockIdx.x;
    const int c0 = s * SL;
    const int nc = min(SL, C - c0);

    __shared__ __align__(16) float sW2[SL * 64];
    __shared__ float sM[2][72];
    __shared__ float sPhi[SL * 64];

    const int tid = threadIdx.x;
    for (int e = tid; e < nc * 16; e += 128)
        ((float4*)sPhi)[e] = ((const float4*)(g_Phi + c0 * 64))[e];
    if (tid < 64) {
        const int i = tid >> 3, j = tid & 7;
        sM[0][i*9+j] = (i == j) ? 1.f : 0.f;
    }
    __syncthreads();

    // backward suffix products of Phi (serial nc steps, 64 threads)
    int pb = 0;
    for (int jj = nc - 1; jj >= 0; jj--) {
        if (tid < 64) {
            const int i = tid >> 3, j = tid & 7;
            sW2[jj*64 + tid] = sM[pb][i*9+j];
            const float* ph = sPhi + jj * 64;
            float m = 0.f;
            #pragma unroll
            for (int k = 0; k < 8; k++)
                m = fmaf(sM[pb][i*9+k], ph[k*8 + j], m);
            sM[pb ^ 1][i*9+j] = m;
        }
        pb ^= 1;
        __syncthreads();
    }
    if (blockIdx.y == 0 && tid < 64) {
        const int i = tid >> 3, j = tid & 7;
        g_Psi[s*64 + tid] = sM[pb][i*9+j];
    }

    const int b = blockIdx.y * 128 + tid;
    const bool ok = (b < B);
    const int bs = ok ? b : 0;

    float acc[8];
    #pragma unroll
    for (int i = 0; i < 8; i++) acc[i] = 0.f;

    for (int jj = 0; jj < nc; jj++) {
        const float4* ep = (const float4*)(g_E + ((size_t)(c0 + jj) * B + bs) * 8);
        const float4 e0 = ep[0], e1 = ep[1];
        const float* w = sW2 + jj * 64;
        #pragma unroll
        for (int i = 0; i < 8; i++) {
            float a = acc[i];
            a = fmaf(w[i*8+0], e0.x, a); a = fmaf(w[i*8+1], e0.y, a);
            a = fmaf(w[i*8+2], e0.z, a); a = fmaf(w[i*8+3], e0.w, a);
            a = fmaf(w[i*8+4], e1.x, a); a = fmaf(w[i*8+5], e1.y, a);
            a = fmaf(w[i*8+6], e1.z, a); a = fmaf(w[i*8+7], e1.w, a);
            acc[i] = a;
        }
    }
    if (ok) {
        float4* eo = (float4*)(g_E2 + ((size_t)s * B + b) * 8);
        eo[0] = make_float4(acc[0], acc[1], acc[2], acc[3]);
        eo[1] = make_float4(acc[4], acc[5], acc[6], acc[7]);
    }
}

// ============================ combineB =====================================

__global__ void __launch_bounds__(256) combineB_kernel(
    const float* __restrict__ x0, int B, int SC)
{
    __shared__ float sPsi[SCMAX * 64];
    const int tid = threadIdx.x;
    for (int e = tid; e < SC * 64; e += 256) sPsi[e] = g_Psi[e];
    __syncthreads();

    const int b = blockIdx.x * 256 + tid;
    const bool ok = (b < B);
    const int bs = ok ? b : 0;

    float x[8];
    {
        const float4* xp = (const float4*)(x0 + bs * 8);
        float4 a = xp[0], b4 = xp[1];
        x[0]=a.x; x[1]=a.y; x[2]=a.z; x[3]=a.w;
        x[4]=b4.x; x[5]=b4.y; x[6]=b4.z; x[7]=b4.w;
    }

    for (int s = 0; s < SC; s++) {
        if (ok) {
            float4* xo = (float4*)(g_X2 + ((size_t)s * B + b) * 8);
            xo[0] = make_float4(x[0], x[1], x[2], x[3]);
            xo[1] = make_float4(x[4], x[5], x[6], x[7]);
        }
        const float4* ep = (const float4*)(g_E2 + ((size_t)s * B + bs) * 8);
        const float4 e0 = ep[0], e1 = ep[1];
        const float* pr = sPsi + s * 64;
        float xn[8];
        #pragma unroll
        for (int i = 0; i < 8; i++) {
            float a = 0.f;
            #pragma unroll
            for (int k = 0; k < 8; k++) a = fmaf(pr[i*8+k], x[k], a);
            xn[i] = a;
        }
        xn[0]+=e0.x; xn[1]+=e0.y; xn[2]+=e0.z; xn[3]+=e0.w;
        xn[4]+=e1.x; xn[5]+=e1.y; xn[6]+=e1.z; xn[7]+=e1.w;
        #pragma unroll
        for (int i = 0; i < 8; i++) x[i] = xn[i];
    }
}

// ============================ combineC =====================================

__global__ void __launch_bounds__(128) combineC_kernel(int B, int C)
{
    const int s  = blockIdx.x;
    const int c0 = s * SL;
    const int nc = min(SL, C - c0);

    __shared__ __align__(16) float sPhi[SL * 64];
    const int tid = threadIdx.x;
    for (int e = tid; e < nc * 16; e += 128)
        ((float4*)sPhi)[e] = ((const float4*)(g_Phi + c0 * 64))[e];
    __syncthreads();

    const int b = blockIdx.y * 128 + tid;
    const bool ok = (b < B);
    const int bs = ok ? b : 0;

    float x[8];
    {
        const float4* xp = (const float4*)(g_X2 + ((size_t)s * B + bs) * 8);
        float4 a = xp[0], b4 = xp[1];
        x[0]=a.x; x[1]=a.y; x[2]=a.z; x[3]=a.w;
        x[4]=b4.x; x[5]=b4.y; x[6]=b4.z; x[7]=b4.w;
    }

    for (int jj = 0; jj < nc; jj++) {
        const int c = c0 + jj;
        if (ok) {
            float4* xo = (float4*)(g_X + ((size_t)c * B + b) * 8);
            xo[0] = make_float4(x[0], x[1], x[2], x[3]);
            xo[1] = make_float4(x[4], x[5], x[6], x[7]);
        }
        if (jj < nc - 1) {
            const float4* ep = (const float4*)(g_E + ((size_t)c * B + bs) * 8);
            const float4 e0 = ep[0], e1 = ep[1];
            const float* pr = sPhi + jj * 64;
            float xn[8];
            #pragma unroll
            for (int i = 0; i < 8; i++) {
                float a = 0.f;
                #pragma unroll
                for (int k = 0; k < 8; k++) a = fmaf(pr[i*8+k], x[k], a);
                xn[i] = a;
            }
            xn[0]+=e0.x; xn[1]+=e0.y; xn[2]+=e0.z; xn[3]+=e0.w;
            xn[4]+=e1.x; xn[5]+=e1.y; xn[6]+=e1.z; xn[7]+=e1.w;
            #pragma unroll
            for (int i = 0; i < 8; i++) x[i] = xn[i];
        }
    }
}

// ============================ scan =========================================
// 2 chains/thread; fast path prefetches ALL y into registers before the
// serial chain, so LDG latency fully overlaps the dependent FMA chain.

__global__ void __launch_bounds__(NT, 1) scan_kernel(
    const float* __restrict__ Y, float* __restrict__ traj, int B, int T)
{
    const int c  = blockIdx.x;
    const int L0 = c * LCH;
    const int Lc = min(LCH, T - L0);
    const int tconv = g_tconv;

    __shared__ __align__(16) float sAK[LCH * 128];
    __shared__ __align__(16) float sOut[NB * SROW];

    const int tid = threadIdx.x;
    load_sAK(sAK, L0, Lc, tconv, tid, NT);

    const int bA = blockIdx.y * NB + tid;
    const int bsA = (bA < B) ? bA : 0;
    const int bB = bA + NT;
    const int bsB = (bB < B) ? bB : 0;
    const float4* yA = (const float4*)(Y + ((size_t)bsA * T + L0) * 8);
    const float4* yB = (const float4*)(Y + ((size_t)bsB * T + L0) * 8);
    float* oA = sOut + tid * SROW;
    float* oB = sOut + (tid + NT) * SROW;

    float xA[8], xB[8];
    {
        const float4* xp = (const float4*)(g_X + ((size_t)c * B + bsA) * 8);
        float4 a = xp[0], b4 = xp[1];
        xA[0]=a.x; xA[1]=a.y; xA[2]=a.z; xA[3]=a.w;
        xA[4]=b4.x; xA[5]=b4.y; xA[6]=b4.z; xA[7]=b4.w;
    }
    {
        const float4* xp = (const float4*)(g_X + ((size_t)c * B + bsB) * 8);
        float4 a = xp[0], b4 = xp[1];
        xB[0]=a.x; xB[1]=a.y; xB[2]=a.z; xB[3]=a.w;
        xB[4]=b4.x; xB[5]=b4.y; xB[6]=b4.z; xB[7]=b4.w;
    }

    if (Lc == LCH) {
        // prefetch the entire y window for both chains (branch-free)
        float4 vA[2 * LCH], vB[2 * LCH];
        #pragma unroll
        for (int q = 0; q < 2 * LCH; q++) { vA[q] = yA[q]; vB[q] = yB[q]; }
        __syncthreads();   // sAK ready

        #pragma unroll
        for (int jj = 0; jj < LCH; jj++) {
            const float4 ya0 = vA[2*jj], ya1 = vA[2*jj + 1];
            const float4 yb0 = vB[2*jj], yb1 = vB[2*jj + 1];
            const float* a = sAK + jj * 128;
            float xnA[8], xnB[8];
            #pragma unroll
            for (int i = 0; i < 8; i++) {
                const float* ar = a + i * 8;
                const float* kr = a + 64 + i * 8;
                float sA0 = ar[0] * xA[0];
                float sA1 = kr[0] * ya0.x;
                float sB0 = ar[0] * xB[0];
                float sB1 = kr[0] * yb0.x;
                sA0 = fmaf(ar[1], xA[1], sA0);  sB0 = fmaf(ar[1], xB[1], sB0);
                sA1 = fmaf(kr[1], ya0.y, sA1);  sB1 = fmaf(kr[1], yb0.y, sB1);
                sA0 = fmaf(ar[2], xA[2], sA0);  sB0 = fmaf(ar[2], xB[2], sB0);
                sA1 = fmaf(kr[2], ya0.z, sA1);  sB1 = fmaf(kr[2], yb0.z, sB1);
                sA0 = fmaf(ar[3], xA[3], sA0);  sB0 = fmaf(ar[3], xB[3], sB0);
                sA1 = fmaf(kr[3], ya0.w, sA1);  sB1 = fmaf(kr[3], yb0.w, sB1);
                sA0 = fmaf(ar[4], xA[4], sA0);  sB0 = fmaf(ar[4], xB[4], sB0);
                sA1 = fmaf(kr[4], ya1.x, sA1);  sB1 = fmaf(kr[4], yb1.x, sB1);
                sA0 = fmaf(ar[5], xA[5], sA0);  sB0 = fmaf(ar[5], xB[5], sB0);
                sA1 = fmaf(kr[5], ya1.y, sA1);  sB1 = fmaf(kr[5], yb1.y, sB1);
                sA0 = fmaf(ar[6], xA[6], sA0);  sB0 = fmaf(ar[6], xB[6], sB0);
                sA1 = fmaf(kr[6], ya1.z, sA1);  sB1 = fmaf(kr[6], yb1.z, sB1);
                sA0 = fmaf(ar[7], xA[7], sA0);  sB0 = fmaf(ar[7], xB[7], sB0);
                sA1 = fmaf(kr[7], ya1.w, sA1);  sB1 = fmaf(kr[7], yb1.w, sB1);
                xnA[i] = sA0 + sA1;
                xnB[i] = sB0 + sB1;
            }
            #pragma unroll
            for (int i = 0; i < 8; i++) { xA[i] = xnA[i]; xB[i] = xnB[i]; }
            ((float4*)oA)[2*jj]     = make_float4(xA[0], xA[1], xA[2], xA[3]);
            ((float4*)oA)[2*jj + 1] = make_float4(xA[4], xA[5], xA[6], xA[7]);
            ((float4*)oB)[2*jj]     = make_float4(xB[0], xB[1], xB[2], xB[3]);
            ((float4*)oB)[2*jj + 1] = make_float4(xB[4], xB[5], xB[6], xB[7]);
        }
    } else {
        __syncthreads();   // sAK ready
        for (int jj = 0; jj < Lc; jj++) {
            const float4 ya0 = yA[2*jj], ya1 = yA[2*jj + 1];
            const float4 yb0 = yB[2*jj], yb1 = yB[2*jj + 1];
            const float* a = sAK + jj * 128;
            float xnA[8], xnB[8];
            #pragma unroll
            for (int i = 0; i < 8; i++) {
                const float* ar = a + i * 8;
                const float* kr = a + 64 + i * 8;
                float sA0 = ar[0] * xA[0];
                float sA1 = kr[0] * ya0.x;
                float sB0 = ar[0] * xB[0];
                float sB1 = kr[0] * yb0.x;
                sA0 = fmaf(ar[1], xA[1], sA0);  sB0 = fmaf(ar[1], xB[1], sB0);
                sA1 = fmaf(kr[1], ya0.y, sA1);  sB1 = fmaf(kr[1], yb0.y, sB1);
                sA0 = fmaf(ar[2], xA[2], sA0);  sB0 = fmaf(ar[2], xB[2], sB0);
                sA1 = fmaf(kr[2], ya0.z, sA1);  sB1 = fmaf(kr[2], yb0.z, sB1);
                sA0 = fmaf(ar[3], xA[3], sA0);  sB0 = fmaf(ar[3], xB[3], sB0);
                sA1 = fmaf(kr[3], ya0.w, sA1);  sB1 = fmaf(kr[3], yb0.w, sB1);
                sA0 = fmaf(ar[4], xA[4], sA0);  sB0 = fmaf(ar[4], xB[4], sB0);
                sA1 = fmaf(kr[4], ya1.x, sA1);  sB1 = fmaf(kr[4], yb1.x, sB1);
                sA0 = fmaf(ar[5], xA[5], sA0);  sB0 = fmaf(ar[5], xB[5], sB0);
                sA1 = fmaf(kr[5], ya1.y, sA1);  sB1 = fmaf(kr[5], yb1.y, sB1);
                sA0 = fmaf(ar[6], xA[6], sA0);  sB0 = fmaf(ar[6], xB[6], sB0);
                sA1 = fmaf(kr[6], ya1.z, sA1);  sB1 = fmaf(kr[6], yb1.z, sB1);
                sA0 = fmaf(ar[7], xA[7], sA0);  sB0 = fmaf(ar[7], xB[7], sB0);
                sA1 = fmaf(kr[7], ya1.w, sA1);  sB1 = fmaf(kr[7], yb1.w, sB1);
                xnA[i] = sA0 + sA1;
                xnB[i] = sB0 + sB1;
            }
            #pragma unroll
            for (int i = 0; i < 8; i++) { xA[i] = xnA[i]; xB[i] = xnB[i]; }
            ((float4*)oA)[2*jj]     = make_float4(xA[0], xA[1], xA[2], xA[3]);
            ((float4*)oA)[2*jj + 1] = make_float4(xA[4], xA[5], xA[6], xA[7]);
            ((float4*)oB)[2*jj]     = make_float4(xB[0], xB[1], xB[2], xB[3]);
            ((float4*)oB)[2*jj + 1] = make_float4(xB[4], xB[5], xB[6], xB[7]);
        }
    }
    __syncthreads();

    // coalesced store of the output tile
    {
        float4* T4 = (float4*)traj;
        const int b0 = blockIdx.y * NB;
        for (int idx = tid; idx < NB * 2 * LCH; idx += NT) {
            const int row = idx / (2 * LCH);
            const int col = idx - row * (2 * LCH);
            const int b = b0 + row;
            if (b < B && col < 2 * Lc)
                T4[((size_t)b * T + L0) * 2 + col] =
                    ((const float4*)(sOut + row * SROW))[col];
        }
    }
}

// ============================ launch =======================================

extern "C" void kernel_launch(void* const* d_in, const int* in_sizes, int n_in,
                              void* d_out, int out_size)
{
    const float* Y  = (const float*)d_in[0];
    const float* F  = (const float*)d_in[1];
    const float* G  = (const float*)d_in[2];
    const float* H  = (const float*)d_in[3];
    const float* Q  = (const float*)d_in[4];
    const float* R  = (const float*)d_in[5];
    const float* x0 = (const float*)d_in[6];
    const float* P0 = (const float*)d_in[7];

    const int B  = in_sizes[6] / 8;
    const int T  = in_sizes[0] / (B * 8);
    const int C  = (T + LCH - 1) / LCH;
    const int SC = (C + SL - 1) / SL;

    float* traj = (float*)d_out;                 // (B, T, 8)
    float* Ps   = traj + (size_t)B * T * 8;      // (T, 8, 8)

    riccati_kernel<<<1, 64>>>(F, G, H, Q, R, P0, Ps, T);
    wprep_kernel<<<C, 64>>>(Ps, T);
    {
        dim3 grid(C, (B + 255) / 256);
        ends_kernel<<<grid, 128>>>(Y, B, T);
    }
    {
        dim3 grid(SC, (B + 127) / 128);
        combineA_kernel<<<grid, 128>>>(B, C);
    }
    combineB_kernel<<<(B + 255) / 256, 256>>>(x0, B, SC);
    {
        dim3 grid(SC, (B + 127) / 128);
        combineC_kernel<<<grid, 128>>>(B, C);
    }
    {
        dim3 grid(C, (B + NB - 1) / NB);
        scan_kernel<<<grid, NT>>>(Y, traj, B, T);
    }
}